// round 1
// baseline (speedup 1.0000x reference)
#include <cuda_runtime.h>
#include <cuda_bf16.h>

// ---------------------------------------------------------------------------
// VGNN sparse belief-propagation-style GNN, fp32 baseline.
//
// Shapes (fixed):
//   N_NODES=10000, N_FACTORS=20000, S=30000 segments, E=80000 edges
//   STATE_DIM=64, MSG_DIM=64, HID=128, N_STEPS=10
//
// d_in order (metadata):
//   0 row(int32,80000) 1 col(int32,80000) 2 edge_attr(f32,320000)
//   3 n_nodes 4 num_segments
//   5 mp_w1(128x132) 6 mp_b1(128) 7 mp_w2(128x128) 8 mp_b2(128)
//   9 mp_w3(64x128) 10 mp_b3(64)
//   11 w_ih(256x64) 12 w_hh(256x64) 13 b_ih(256) 14 b_hh(256)
//   15 ro_w1(128x64) 16 ro_b1(128) 17 ro_w2(128x128) 18 ro_b2(128)
//   19 ro_w3(2x128) 20 ro_b3(2)
// out: float32, 10000 x 2 softmax probs
// ---------------------------------------------------------------------------

#define N_NODES   10000
#define N_FACTORS 20000
#define N_SEGS    30000
#define N_EDGES   80000
#define SD        64
#define HID       128
#define N_STEPS   10
#define NTHREADS  256
#define NBLK      148

__device__ float g_h[N_SEGS * SD];
__device__ float g_c[N_SEGS * SD];
__device__ float g_nm[N_SEGS * SD];

__device__ __forceinline__ float fsigmoid(float x) {
    return 1.0f / (1.0f + __expf(-x));
}
__device__ __forceinline__ float ftanh(float x) {
    return 2.0f * fsigmoid(2.0f * x) - 1.0f;
}

// ---------------------------------------------------------------------------
// Cooperative transposed weight load: W is [N][K] row-major in gmem,
// wT is [K][WS] in smem with wT[k*WS + o] = W[o*K + k].  WS = N+4 keeps the
// STS conflict degree at 4 and GEMM-side float4 reads conflict-free.
// ---------------------------------------------------------------------------
__device__ __forceinline__ void load_wT(int tid, const float* __restrict__ W,
                                        float* __restrict__ wT,
                                        int N, int K, int WS) {
    for (int idx = tid; idx < N * K; idx += NTHREADS) {
        int o = idx / K;
        int k = idx - o * K;
        wT[k * WS + o] = W[idx];
    }
}

// ---------------------------------------------------------------------------
// 32-row tile GEMM: out[32][N] = act( xs[32][KSTR(first K used)] * wT + bias )
// Per-thread micro-tile: EPT rows x 4 cols.  Weight reads: one LDS.128 per k
// per thread, conflict-free.  Activation reads: warp-broadcast LDS.
// ---------------------------------------------------------------------------
template <int K, int N, int KSTR, bool RELU>
__device__ __forceinline__ void gemm32(int tid,
                                       const float* __restrict__ xs,
                                       const float* __restrict__ wT,
                                       const float* __restrict__ bias,
                                       float* __restrict__ out) {
    constexpr int WS  = N + 4;
    constexpr int OG  = N / 4;             // col groups
    constexpr int EPT = 32 * OG / NTHREADS; // rows per thread
    static_assert(NTHREADS % OG == 0, "");
    const int oo = tid % OG;
    const int eo = tid / OG;
    const int o  = oo * 4;
    const int e0 = eo * EPT;

    float acc[EPT][4];
    const float4 b4 = *reinterpret_cast<const float4*>(bias + o);
#pragma unroll
    for (int ii = 0; ii < EPT; ++ii) {
        acc[ii][0] = b4.x; acc[ii][1] = b4.y; acc[ii][2] = b4.z; acc[ii][3] = b4.w;
    }

#pragma unroll 4
    for (int k = 0; k < K; ++k) {
        const float4 w = *reinterpret_cast<const float4*>(wT + k * WS + o);
#pragma unroll
        for (int ii = 0; ii < EPT; ++ii) {
            const float x = xs[(e0 + ii) * KSTR + k];
            acc[ii][0] += x * w.x;
            acc[ii][1] += x * w.y;
            acc[ii][2] += x * w.z;
            acc[ii][3] += x * w.w;
        }
    }

#pragma unroll
    for (int ii = 0; ii < EPT; ++ii) {
        float4 r;
        r.x = acc[ii][0]; r.y = acc[ii][1]; r.z = acc[ii][2]; r.w = acc[ii][3];
        if (RELU) {
            r.x = fmaxf(r.x, 0.f); r.y = fmaxf(r.y, 0.f);
            r.z = fmaxf(r.z, 0.f); r.w = fmaxf(r.w, 0.f);
        }
        *reinterpret_cast<float4*>(out + (e0 + ii) * N + o) = r;
    }
}

// ---------------------------------------------------------------------------
// init: h0 = 0 except h0[factors,0]=1 ; c0 = 0 ; nm = 0
// ---------------------------------------------------------------------------
__global__ void k_init() {
    int idx = blockIdx.x * blockDim.x + threadIdx.x;
    if (idx >= N_SEGS * SD) return;
    int s = idx >> 6;
    int d = idx & 63;
    g_h[idx]  = (s >= N_NODES && d == 0) ? 1.0f : 0.0f;
    g_c[idx]  = 0.0f;
    g_nm[idx] = 0.0f;
}

// ---------------------------------------------------------------------------
// Edge kernel: fused gather + 3-layer MLP + atomic scatter.
// smem layout (floats):
// ---------------------------------------------------------------------------
#define E_OW1 0                       // [132][132]  (K=132, WS=128+4)
#define E_OW2 (E_OW1 + 132 * 132)     // [128][132]
#define E_OW3 (E_OW2 + 128 * 132)     // [128][68]
#define E_OB1 (E_OW3 + 128 * 68)
#define E_OB2 (E_OB1 + 128)
#define E_OB3 (E_OB2 + 128)
#define E_OXS (E_OB3 + 64)            // [32][132], reused as h2 [32][128]
#define E_OH1 (E_OXS + 32 * 132)      // [32][128], reused as m [32][64]
#define E_SMEM_FLOATS (E_OH1 + 32 * 128)
#define E_SMEM_BYTES (E_SMEM_FLOATS * 4)

__global__ void __launch_bounds__(NTHREADS, 1)
k_edge(const int* __restrict__ row, const int* __restrict__ col,
       const float* __restrict__ eattr,
       const float* __restrict__ w1, const float* __restrict__ b1,
       const float* __restrict__ w2, const float* __restrict__ b2,
       const float* __restrict__ w3, const float* __restrict__ b3) {
    extern __shared__ float sm[];
    const int tid = threadIdx.x;

    load_wT(tid, w1, sm + E_OW1, 128, 132, 132);
    load_wT(tid, w2, sm + E_OW2, 128, 128, 132);
    load_wT(tid, w3, sm + E_OW3, 64, 128, 68);
    for (int i = tid; i < 128; i += NTHREADS) {
        sm[E_OB1 + i] = b1[i];
        sm[E_OB2 + i] = b2[i];
        if (i < 64) sm[E_OB3 + i] = b3[i];
    }
    __syncthreads();

    const int n_tiles = N_EDGES / 32;  // 2500 exactly
    for (int t = blockIdx.x; t < n_tiles; t += gridDim.x) {
        const int base = t * 32;
        // gather x = [h[row] | h[col] | edge_attr]  (32 x 132)
        for (int idx = tid; idx < 32 * 132; idx += NTHREADS) {
            const int i = idx / 132;
            const int k = idx - i * 132;
            const int e = base + i;
            float v;
            if (k < 64)       v = g_h[row[e] * SD + k];
            else if (k < 128) v = g_h[col[e] * SD + (k - 64)];
            else              v = eattr[e * 4 + (k - 128)];
            sm[E_OXS + idx] = v;
        }
        __syncthreads();

        gemm32<132, 128, 132, true >(tid, sm + E_OXS, sm + E_OW1, sm + E_OB1, sm + E_OH1);
        __syncthreads();
        gemm32<128, 128, 128, true >(tid, sm + E_OH1, sm + E_OW2, sm + E_OB2, sm + E_OXS);
        __syncthreads();
        gemm32<128,  64, 128, false>(tid, sm + E_OXS, sm + E_OW3, sm + E_OB3, sm + E_OH1);
        __syncthreads();

        // scatter messages into nm[col]
        for (int idx = tid; idx < 32 * 64; idx += NTHREADS) {
            const int i = idx >> 6;
            const int d = idx & 63;
            const int c = col[base + i];
            atomicAdd(&g_nm[c * SD + d], sm[E_OH1 + i * 64 + d]);
        }
        __syncthreads();
    }
}

// ---------------------------------------------------------------------------
// LSTM kernel: gates = nm*w_ih^T + h*w_hh^T + b ; update h,c ; zero nm
// ---------------------------------------------------------------------------
#define L_OWI 0                      // [64][260]
#define L_OWH (L_OWI + 64 * 260)     // [64][260]
#define L_OB  (L_OWH + 64 * 260)     // [256]  (b_ih + b_hh)
#define L_ONM (L_OB + 256)           // [32][64]
#define L_OHS (L_ONM + 32 * 64)      // [32][64]
#define L_OG  (L_OHS + 32 * 64)      // [32][256]
#define L_SMEM_FLOATS (L_OG + 32 * 256)
#define L_SMEM_BYTES (L_SMEM_FLOATS * 4)

__global__ void __launch_bounds__(NTHREADS, 1)
k_lstm(const float* __restrict__ wih, const float* __restrict__ whh,
       const float* __restrict__ bih, const float* __restrict__ bhh) {
    extern __shared__ float sm[];
    const int tid = threadIdx.x;

    load_wT(tid, wih, sm + L_OWI, 256, 64, 260);
    load_wT(tid, whh, sm + L_OWH, 256, 64, 260);
    for (int i = tid; i < 256; i += NTHREADS) sm[L_OB + i] = bih[i] + bhh[i];
    __syncthreads();

    const int n_tiles = (N_SEGS + 31) / 32;  // 938
    for (int t = blockIdx.x; t < n_tiles; t += gridDim.x) {
        const int base = t * 32;
        for (int idx = tid; idx < 32 * 64; idx += NTHREADS) {
            const int i = idx >> 6;
            const int d = idx & 63;
            const int s = base + i;
            const bool ok = (s < N_SEGS);
            sm[L_ONM + idx] = ok ? g_nm[s * SD + d] : 0.f;
            sm[L_OHS + idx] = ok ? g_h[s * SD + d] : 0.f;
        }
        __syncthreads();

        // dual-input GEMM: 32 segs x 256 gate outputs, K=64
        {
            const int oo = tid & 63;       // 64 col groups of 4
            const int eo = tid >> 6;       // 4 row groups of 8
            const int o  = oo * 4;
            const int e0 = eo * 8;
            float acc[8][4];
            const float4 b4 = *reinterpret_cast<const float4*>(sm + L_OB + o);
#pragma unroll
            for (int ii = 0; ii < 8; ++ii) {
                acc[ii][0] = b4.x; acc[ii][1] = b4.y; acc[ii][2] = b4.z; acc[ii][3] = b4.w;
            }
#pragma unroll 4
            for (int k = 0; k < 64; ++k) {
                const float4 wa = *reinterpret_cast<const float4*>(sm + L_OWI + k * 260 + o);
                const float4 wb = *reinterpret_cast<const float4*>(sm + L_OWH + k * 260 + o);
#pragma unroll
                for (int ii = 0; ii < 8; ++ii) {
                    const float x  = sm[L_ONM + (e0 + ii) * 64 + k];
                    const float hh = sm[L_OHS + (e0 + ii) * 64 + k];
                    acc[ii][0] += x * wa.x + hh * wb.x;
                    acc[ii][1] += x * wa.y + hh * wb.y;
                    acc[ii][2] += x * wa.z + hh * wb.z;
                    acc[ii][3] += x * wa.w + hh * wb.w;
                }
            }
#pragma unroll
            for (int ii = 0; ii < 8; ++ii) {
                float4 r;
                r.x = acc[ii][0]; r.y = acc[ii][1]; r.z = acc[ii][2]; r.w = acc[ii][3];
                *reinterpret_cast<float4*>(sm + L_OG + (e0 + ii) * 256 + o) = r;
            }
        }
        __syncthreads();

        // elementwise LSTM update + zero nm for next step
        for (int idx = tid; idx < 32 * 64; idx += NTHREADS) {
            const int i = idx >> 6;
            const int d = idx & 63;
            const int s = base + i;
            if (s < N_SEGS) {
                const float gi = sm[L_OG + i * 256 + d];
                const float gf = sm[L_OG + i * 256 + 64 + d];
                const float gg = sm[L_OG + i * 256 + 128 + d];
                const float go = sm[L_OG + i * 256 + 192 + d];
                const float cold = g_c[s * SD + d];
                const float cn = fsigmoid(gf) * cold + fsigmoid(gi) * ftanh(gg);
                const float hn = fsigmoid(go) * ftanh(cn);
                g_c[s * SD + d]  = cn;
                g_h[s * SD + d]  = hn;
                g_nm[s * SD + d] = 0.0f;
            }
        }
        __syncthreads();
    }
}

// ---------------------------------------------------------------------------
// Readout: h[:10000] -> 128 relu -> 128 relu -> 2 -> softmax
// ---------------------------------------------------------------------------
#define R_OW1 0                       // [64][132]
#define R_OW2 (R_OW1 + 64 * 132)      // [128][132]
#define R_OW3 (R_OW2 + 128 * 132)     // [2][128]
#define R_OB1 (R_OW3 + 256)
#define R_OB2 (R_OB1 + 128)
#define R_OB3 (R_OB2 + 128)
#define R_OXS (R_OB3 + 4)             // [32][64]
#define R_OH1 (R_OXS + 32 * 64)       // [32][128]
#define R_OH2 (R_OH1 + 32 * 128)      // [32][128]
#define R_OLG (R_OH2 + 32 * 128)      // [32][2]
#define R_SMEM_FLOATS (R_OLG + 64)
#define R_SMEM_BYTES (R_SMEM_FLOATS * 4)

__global__ void __launch_bounds__(NTHREADS, 1)
k_readout(const float* __restrict__ w1, const float* __restrict__ b1,
          const float* __restrict__ w2, const float* __restrict__ b2,
          const float* __restrict__ w3, const float* __restrict__ b3,
          float* __restrict__ out) {
    extern __shared__ float sm[];
    const int tid = threadIdx.x;

    load_wT(tid, w1, sm + R_OW1, 128, 64, 132);
    load_wT(tid, w2, sm + R_OW2, 128, 128, 132);
    for (int i = tid; i < 256; i += NTHREADS) sm[R_OW3 + i] = w3[i];
    for (int i = tid; i < 128; i += NTHREADS) {
        sm[R_OB1 + i] = b1[i];
        sm[R_OB2 + i] = b2[i];
        if (i < 2) sm[R_OB3 + i] = b3[i];
    }
    __syncthreads();

    const int n_tiles = (N_NODES + 31) / 32;  // 313
    for (int t = blockIdx.x; t < n_tiles; t += gridDim.x) {
        const int base = t * 32;
        for (int idx = tid; idx < 32 * 64; idx += NTHREADS) {
            const int i = idx >> 6;
            const int d = idx & 63;
            const int s = base + i;
            sm[R_OXS + idx] = (s < N_NODES) ? g_h[s * SD + d] : 0.f;
        }
        __syncthreads();

        gemm32< 64, 128,  64, true>(tid, sm + R_OXS, sm + R_OW1, sm + R_OB1, sm + R_OH1);
        __syncthreads();
        gemm32<128, 128, 128, true>(tid, sm + R_OH1, sm + R_OW2, sm + R_OB2, sm + R_OH2);
        __syncthreads();

        // final 128 -> 2
        if (tid < 64) {
            const int i = tid >> 1;
            const int j = tid & 1;
            float acc = sm[R_OB3 + j];
#pragma unroll 4
            for (int k = 0; k < 128; ++k)
                acc += sm[R_OH2 + i * 128 + k] * sm[R_OW3 + j * 128 + k];
            sm[R_OLG + i * 2 + j] = acc;
        }
        __syncthreads();

        if (tid < 32) {
            const int s = base + tid;
            if (s < N_NODES) {
                const float l0 = sm[R_OLG + tid * 2];
                const float l1 = sm[R_OLG + tid * 2 + 1];
                const float m  = fmaxf(l0, l1);
                const float e0 = __expf(l0 - m);
                const float e1 = __expf(l1 - m);
                const float inv = 1.0f / (e0 + e1);
                out[s * 2]     = e0 * inv;
                out[s * 2 + 1] = e1 * inv;
            }
        }
        __syncthreads();
    }
}

// ---------------------------------------------------------------------------
extern "C" void kernel_launch(void* const* d_in, const int* in_sizes, int n_in,
                              void* d_out, int out_size) {
    const int*   row   = (const int*)  d_in[0];
    const int*   col   = (const int*)  d_in[1];
    const float* eattr = (const float*)d_in[2];
    const float* mp_w1 = (const float*)d_in[5];
    const float* mp_b1 = (const float*)d_in[6];
    const float* mp_w2 = (const float*)d_in[7];
    const float* mp_b2 = (const float*)d_in[8];
    const float* mp_w3 = (const float*)d_in[9];
    const float* mp_b3 = (const float*)d_in[10];
    const float* w_ih  = (const float*)d_in[11];
    const float* w_hh  = (const float*)d_in[12];
    const float* b_ih  = (const float*)d_in[13];
    const float* b_hh  = (const float*)d_in[14];
    const float* ro_w1 = (const float*)d_in[15];
    const float* ro_b1 = (const float*)d_in[16];
    const float* ro_w2 = (const float*)d_in[17];
    const float* ro_b2 = (const float*)d_in[18];
    const float* ro_w3 = (const float*)d_in[19];
    const float* ro_b3 = (const float*)d_in[20];
    float* out = (float*)d_out;

    cudaFuncSetAttribute(k_edge,    cudaFuncAttributeMaxDynamicSharedMemorySize, E_SMEM_BYTES);
    cudaFuncSetAttribute(k_lstm,    cudaFuncAttributeMaxDynamicSharedMemorySize, L_SMEM_BYTES);
    cudaFuncSetAttribute(k_readout, cudaFuncAttributeMaxDynamicSharedMemorySize, R_SMEM_BYTES);

    k_init<<<(N_SEGS * SD + 255) / 256, 256>>>();

    for (int step = 0; step < N_STEPS; ++step) {
        k_edge<<<NBLK, NTHREADS, E_SMEM_BYTES>>>(row, col, eattr,
                                                 mp_w1, mp_b1, mp_w2, mp_b2, mp_w3, mp_b3);
        k_lstm<<<NBLK, NTHREADS, L_SMEM_BYTES>>>(w_ih, w_hh, b_ih, b_hh);
    }

    k_readout<<<NBLK, NTHREADS, R_SMEM_BYTES>>>(ro_w1, ro_b1, ro_w2, ro_b2, ro_w3, ro_b3, out);
}

// round 2
// speedup vs baseline: 1.4320x; 1.4320x over previous
#include <cuda_runtime.h>
#include <cuda_bf16.h>

// ---------------------------------------------------------------------------
// VGNN sparse GNN, fp32, fused persistent-tile kernels. Round 2:
// register-blocked 8x4 micro-tiles, k-vectorized LDS.128, bias/attr via LDG.
// ---------------------------------------------------------------------------

#define N_NODES   10000
#define N_FACTORS 20000
#define N_SEGS    30000
#define N_EDGES   80000
#define SD        64
#define N_STEPS   10
#define NTHREADS  256
#define NBLK      148

__device__ float g_h[N_SEGS * SD];
__device__ float g_c[N_SEGS * SD];
__device__ float g_nm[N_SEGS * SD];

__device__ __forceinline__ float fsigmoid(float x) {
    return 1.0f / (1.0f + __expf(-x));
}
__device__ __forceinline__ float ftanh(float x) {
    return 2.0f * fsigmoid(2.0f * x) - 1.0f;
}

// transposed weight load: W [N][K] gmem row-major -> wT [K][WS] smem
__device__ __forceinline__ void load_wT(int tid, const float* __restrict__ W,
                                        float* __restrict__ wT,
                                        int N, int K, int WS) {
    for (int idx = tid; idx < N * K; idx += NTHREADS) {
        int o = idx / K;
        int k = idx - o * K;
        wT[k * WS + o] = W[idx];
    }
}

// ---------------------------------------------------------------------------
// Edge kernel. 64-edge tiles. smem (floats):
//   w1T [132][128]  (rows 0..127 = h parts, 128..131 = attr part)
//   w2T [128][128]
//   w3T [128][64]
//   xs  [64][128]   gather buf, then reused as h2 output of layer 2
//   h1  [64][128]   layer-1 output, then reused as message buf [64][64]
// ---------------------------------------------------------------------------
#define E_W1 0
#define E_W2 (E_W1 + 132 * 128)
#define E_W3 (E_W2 + 128 * 128)
#define E_XS (E_W3 + 128 * 64)
#define E_H1 (E_XS + 64 * 128)
#define E_SMEM_FLOATS (E_H1 + 64 * 128)
#define E_SMEM_BYTES (E_SMEM_FLOATS * 4)   // 231424 <= 232448

// generic tile GEMM: out[64][N] = act( xs[64][128(K used)] * wT + bias )
// per-thread: EPT rows x 4 cols, k vectorized by 4.
template <int N, int K, bool RELU>
__device__ __forceinline__ void gemm_tile64(int tid,
                                            const float* __restrict__ xs,
                                            const float* __restrict__ wT,
                                            const float* __restrict__ bias_g,
                                            float* __restrict__ out) {
    constexpr int OG  = N / 4;
    constexpr int RG  = NTHREADS / OG;
    constexpr int EPT = 64 / RG;
    const int oo = tid % OG;
    const int eo = tid / OG;
    const int o  = oo * 4;
    const int e0 = eo * EPT;

    float acc[EPT][4];
    const float4 b4 = __ldg(reinterpret_cast<const float4*>(bias_g) + oo);
#pragma unroll
    for (int ii = 0; ii < EPT; ++ii) {
        acc[ii][0] = b4.x; acc[ii][1] = b4.y; acc[ii][2] = b4.z; acc[ii][3] = b4.w;
    }

#pragma unroll 4
    for (int k = 0; k < K; k += 4) {
        const float4 w0 = *reinterpret_cast<const float4*>(wT + (k + 0) * N + o);
        const float4 w1 = *reinterpret_cast<const float4*>(wT + (k + 1) * N + o);
        const float4 w2 = *reinterpret_cast<const float4*>(wT + (k + 2) * N + o);
        const float4 w3 = *reinterpret_cast<const float4*>(wT + (k + 3) * N + o);
#pragma unroll
        for (int ii = 0; ii < EPT; ++ii) {
            const float4 x4 = *reinterpret_cast<const float4*>(xs + (e0 + ii) * 128 + k);
            acc[ii][0] += x4.x * w0.x + x4.y * w1.x + x4.z * w2.x + x4.w * w3.x;
            acc[ii][1] += x4.x * w0.y + x4.y * w1.y + x4.z * w2.y + x4.w * w3.y;
            acc[ii][2] += x4.x * w0.z + x4.y * w1.z + x4.z * w2.z + x4.w * w3.z;
            acc[ii][3] += x4.x * w0.w + x4.y * w1.w + x4.z * w2.w + x4.w * w3.w;
        }
    }

#pragma unroll
    for (int ii = 0; ii < EPT; ++ii) {
        float4 r;
        r.x = acc[ii][0]; r.y = acc[ii][1]; r.z = acc[ii][2]; r.w = acc[ii][3];
        if (RELU) {
            r.x = fmaxf(r.x, 0.f); r.y = fmaxf(r.y, 0.f);
            r.z = fmaxf(r.z, 0.f); r.w = fmaxf(r.w, 0.f);
        }
        *reinterpret_cast<float4*>(out + (e0 + ii) * N + o) = r;
    }
}

__global__ void __launch_bounds__(NTHREADS, 1)
k_edge(const int* __restrict__ row, const int* __restrict__ col,
       const float* __restrict__ eattr,
       const float* __restrict__ w1, const float* __restrict__ b1,
       const float* __restrict__ w2, const float* __restrict__ b2,
       const float* __restrict__ w3, const float* __restrict__ b3) {
    extern __shared__ float sm[];
    const int tid = threadIdx.x;

    load_wT(tid, w1, sm + E_W1, 128, 132, 128);
    load_wT(tid, w2, sm + E_W2, 128, 128, 128);
    load_wT(tid, w3, sm + E_W3, 64, 128, 64);
    __syncthreads();

    const int n_tiles = N_EDGES / 64;  // 1250
    for (int t = blockIdx.x; t < n_tiles; t += gridDim.x) {
        const int base = t * 64;

        // gather xs = [h[row] | h[col]]  (64 x 128), float4 granularity
        for (int idx = tid; idx < 64 * 32; idx += NTHREADS) {
            const int i = idx >> 5;
            const int q = idx & 31;
            const int e = base + i;
            const float4* src = (q < 16)
                ? reinterpret_cast<const float4*>(g_h + row[e] * SD) + q
                : reinterpret_cast<const float4*>(g_h + col[e] * SD) + (q - 16);
            reinterpret_cast<float4*>(sm + E_XS)[i * 32 + q] = *src;
        }
        __syncthreads();

        // ---- layer 1: K = 128 (h parts) + 4 attr cols folded into init ----
        {
            constexpr int OG = 32, EPT = 8;
            const int oo = tid % OG;
            const int eo = tid / OG;
            const int o  = oo * 4;
            const int e0 = eo * EPT;
            const float* wT = sm + E_W1;

            float acc[EPT][4];
            const float4 b4 = __ldg(reinterpret_cast<const float4*>(b1) + oo);
            const float4 wa0 = *reinterpret_cast<const float4*>(wT + 128 * 128 + o);
            const float4 wa1 = *reinterpret_cast<const float4*>(wT + 129 * 128 + o);
            const float4 wa2 = *reinterpret_cast<const float4*>(wT + 130 * 128 + o);
            const float4 wa3 = *reinterpret_cast<const float4*>(wT + 131 * 128 + o);
#pragma unroll
            for (int ii = 0; ii < EPT; ++ii) {
                const float4 a4 = __ldg(reinterpret_cast<const float4*>(eattr) + (base + e0 + ii));
                acc[ii][0] = b4.x + a4.x * wa0.x + a4.y * wa1.x + a4.z * wa2.x + a4.w * wa3.x;
                acc[ii][1] = b4.y + a4.x * wa0.y + a4.y * wa1.y + a4.z * wa2.y + a4.w * wa3.y;
                acc[ii][2] = b4.z + a4.x * wa0.z + a4.y * wa1.z + a4.z * wa2.z + a4.w * wa3.z;
                acc[ii][3] = b4.w + a4.x * wa0.w + a4.y * wa1.w + a4.z * wa2.w + a4.w * wa3.w;
            }

#pragma unroll 4
            for (int k = 0; k < 128; k += 4) {
                const float4 w0 = *reinterpret_cast<const float4*>(wT + (k + 0) * 128 + o);
                const float4 wv1 = *reinterpret_cast<const float4*>(wT + (k + 1) * 128 + o);
                const float4 wv2 = *reinterpret_cast<const float4*>(wT + (k + 2) * 128 + o);
                const float4 wv3 = *reinterpret_cast<const float4*>(wT + (k + 3) * 128 + o);
#pragma unroll
                for (int ii = 0; ii < EPT; ++ii) {
                    const float4 x4 = *reinterpret_cast<const float4*>(sm + E_XS + (e0 + ii) * 128 + k);
                    acc[ii][0] += x4.x * w0.x + x4.y * wv1.x + x4.z * wv2.x + x4.w * wv3.x;
                    acc[ii][1] += x4.x * w0.y + x4.y * wv1.y + x4.z * wv2.y + x4.w * wv3.y;
                    acc[ii][2] += x4.x * w0.z + x4.y * wv1.z + x4.z * wv2.z + x4.w * wv3.z;
                    acc[ii][3] += x4.x * w0.w + x4.y * wv1.w + x4.z * wv2.w + x4.w * wv3.w;
                }
            }
#pragma unroll
            for (int ii = 0; ii < EPT; ++ii) {
                float4 r;
                r.x = fmaxf(acc[ii][0], 0.f); r.y = fmaxf(acc[ii][1], 0.f);
                r.z = fmaxf(acc[ii][2], 0.f); r.w = fmaxf(acc[ii][3], 0.f);
                *reinterpret_cast<float4*>(sm + E_H1 + (e0 + ii) * 128 + o) = r;
            }
        }
        __syncthreads();

        // layer 2: h1 -> xs (reuse)
        gemm_tile64<128, 128, true >(tid, sm + E_H1, sm + E_W2, b2, sm + E_XS);
        __syncthreads();
        // layer 3: xs(h2) -> h1[0:64*64] messages
        gemm_tile64< 64, 128, false>(tid, sm + E_XS, sm + E_W3, b3, sm + E_H1);
        __syncthreads();

        // scatter messages into nm[col]
        for (int idx = tid; idx < 64 * 64; idx += NTHREADS) {
            const int i = idx >> 6;
            const int d = idx & 63;
            atomicAdd(&g_nm[col[base + i] * SD + d], sm[E_H1 + i * 64 + d]);
        }
        __syncthreads();  // protect h1 before next tile's layer 1 writes
    }
}

// ---------------------------------------------------------------------------
// LSTM kernel. 32-seg tiles, OG=64 EPT=8 dual-input GEMM.
// ---------------------------------------------------------------------------
#define L_WI 0
#define L_WH (L_WI + 64 * 256)
#define L_NM (L_WH + 64 * 256)
#define L_HS (L_NM + 32 * 64)
#define L_G  (L_HS + 32 * 64)
#define L_SMEM_FLOATS (L_G + 32 * 256)
#define L_SMEM_BYTES (L_SMEM_FLOATS * 4)   // 180224

__global__ void __launch_bounds__(NTHREADS, 1)
k_lstm(const float* __restrict__ wih, const float* __restrict__ whh,
       const float* __restrict__ bih, const float* __restrict__ bhh) {
    extern __shared__ float sm[];
    const int tid = threadIdx.x;

    load_wT(tid, wih, sm + L_WI, 256, 64, 256);
    load_wT(tid, whh, sm + L_WH, 256, 64, 256);
    __syncthreads();

    const int n_tiles = (N_SEGS + 31) / 32;  // 938
    for (int t = blockIdx.x; t < n_tiles; t += gridDim.x) {
        const int base = t * 32;
        for (int idx = tid; idx < 32 * 16; idx += NTHREADS) {
            const int i = idx >> 4;
            const int q = idx & 15;
            const int s = base + i;
            float4 nmv = make_float4(0.f, 0.f, 0.f, 0.f);
            float4 hv  = make_float4(0.f, 0.f, 0.f, 0.f);
            if (s < N_SEGS) {
                nmv = reinterpret_cast<const float4*>(g_nm + s * SD)[q];
                hv  = reinterpret_cast<const float4*>(g_h  + s * SD)[q];
            }
            reinterpret_cast<float4*>(sm + L_NM)[i * 16 + q] = nmv;
            reinterpret_cast<float4*>(sm + L_HS)[i * 16 + q] = hv;
        }
        __syncthreads();

        // gates[32][256] = nm*w_ih^T + h*w_hh^T + b
        {
            constexpr int OG = 64, EPT = 8;
            const int oo = tid % OG;
            const int eo = tid / OG;
            const int o  = oo * 4;
            const int e0 = eo * EPT;

            float acc[EPT][4];
            const float4 bi = __ldg(reinterpret_cast<const float4*>(bih) + oo);
            const float4 bh = __ldg(reinterpret_cast<const float4*>(bhh) + oo);
#pragma unroll
            for (int ii = 0; ii < EPT; ++ii) {
                acc[ii][0] = bi.x + bh.x; acc[ii][1] = bi.y + bh.y;
                acc[ii][2] = bi.z + bh.z; acc[ii][3] = bi.w + bh.w;
            }

#pragma unroll 2
            for (int k = 0; k < 64; k += 4) {
                const float4 wi0 = *reinterpret_cast<const float4*>(sm + L_WI + (k + 0) * 256 + o);
                const float4 wi1 = *reinterpret_cast<const float4*>(sm + L_WI + (k + 1) * 256 + o);
                const float4 wi2 = *reinterpret_cast<const float4*>(sm + L_WI + (k + 2) * 256 + o);
                const float4 wi3 = *reinterpret_cast<const float4*>(sm + L_WI + (k + 3) * 256 + o);
                const float4 wh0 = *reinterpret_cast<const float4*>(sm + L_WH + (k + 0) * 256 + o);
                const float4 wh1 = *reinterpret_cast<const float4*>(sm + L_WH + (k + 1) * 256 + o);
                const float4 wh2 = *reinterpret_cast<const float4*>(sm + L_WH + (k + 2) * 256 + o);
                const float4 wh3 = *reinterpret_cast<const float4*>(sm + L_WH + (k + 3) * 256 + o);
#pragma unroll
                for (int ii = 0; ii < EPT; ++ii) {
                    const float4 x4 = *reinterpret_cast<const float4*>(sm + L_NM + (e0 + ii) * 64 + k);
                    const float4 h4 = *reinterpret_cast<const float4*>(sm + L_HS + (e0 + ii) * 64 + k);
                    acc[ii][0] += x4.x * wi0.x + x4.y * wi1.x + x4.z * wi2.x + x4.w * wi3.x
                                + h4.x * wh0.x + h4.y * wh1.x + h4.z * wh2.x + h4.w * wh3.x;
                    acc[ii][1] += x4.x * wi0.y + x4.y * wi1.y + x4.z * wi2.y + x4.w * wi3.y
                                + h4.x * wh0.y + h4.y * wh1.y + h4.z * wh2.y + h4.w * wh3.y;
                    acc[ii][2] += x4.x * wi0.z + x4.y * wi1.z + x4.z * wi2.z + x4.w * wi3.z
                                + h4.x * wh0.z + h4.y * wh1.z + h4.z * wh2.z + h4.w * wh3.z;
                    acc[ii][3] += x4.x * wi0.w + x4.y * wi1.w + x4.z * wi2.w + x4.w * wi3.w
                                + h4.x * wh0.w + h4.y * wh1.w + h4.z * wh2.w + h4.w * wh3.w;
                }
            }
#pragma unroll
            for (int ii = 0; ii < EPT; ++ii) {
                float4 r;
                r.x = acc[ii][0]; r.y = acc[ii][1]; r.z = acc[ii][2]; r.w = acc[ii][3];
                *reinterpret_cast<float4*>(sm + L_G + (e0 + ii) * 256 + o) = r;
            }
        }
        __syncthreads();

        // elementwise LSTM update + zero nm for next step
        for (int idx = tid; idx < 32 * 64; idx += NTHREADS) {
            const int i = idx >> 6;
            const int d = idx & 63;
            const int s = base + i;
            if (s < N_SEGS) {
                const float gi = sm[L_G + i * 256 + d];
                const float gf = sm[L_G + i * 256 + 64 + d];
                const float gg = sm[L_G + i * 256 + 128 + d];
                const float go = sm[L_G + i * 256 + 192 + d];
                const float cold = g_c[s * SD + d];
                const float cn = fsigmoid(gf) * cold + fsigmoid(gi) * ftanh(gg);
                const float hn = fsigmoid(go) * ftanh(cn);
                g_c[s * SD + d]  = cn;
                g_h[s * SD + d]  = hn;
                g_nm[s * SD + d] = 0.0f;
            }
        }
        __syncthreads();
    }
}

// ---------------------------------------------------------------------------
__global__ void k_init() {
    int idx = blockIdx.x * blockDim.x + threadIdx.x;
    if (idx >= N_SEGS * SD) return;
    int s = idx >> 6;
    int d = idx & 63;
    g_h[idx]  = (s >= N_NODES && d == 0) ? 1.0f : 0.0f;
    g_c[idx]  = 0.0f;
    g_nm[idx] = 0.0f;
}

// ---------------------------------------------------------------------------
// Readout: h[:10000] -> 128 relu -> 128 relu -> 2 -> softmax.
// 64-row tiles with the shared gemm_tile64.
// ---------------------------------------------------------------------------
#define R_W1 0
#define R_W2 (R_W1 + 64 * 128)
#define R_W3 (R_W2 + 128 * 128)         // [2][128] plain
#define R_XS (R_W3 + 256)               // [64][128] (only first 64 cols used for L1)
#define R_H1 (R_XS + 64 * 128)          // [64][128]
#define R_LG (R_H1 + 64 * 128)          // [64][2]
#define R_SMEM_FLOATS (R_LG + 128)
#define R_SMEM_BYTES (R_SMEM_FLOATS * 4)

__global__ void __launch_bounds__(NTHREADS, 1)
k_readout(const float* __restrict__ w1, const float* __restrict__ b1,
          const float* __restrict__ w2, const float* __restrict__ b2,
          const float* __restrict__ w3, const float* __restrict__ b3,
          float* __restrict__ out) {
    extern __shared__ float sm[];
    const int tid = threadIdx.x;

    load_wT(tid, w1, sm + R_W1, 128, 64, 128);
    load_wT(tid, w2, sm + R_W2, 128, 128, 128);
    for (int i = tid; i < 256; i += NTHREADS) sm[R_W3 + i] = w3[i];
    __syncthreads();

    const int n_tiles = (N_NODES + 63) / 64;  // 157
    for (int t = blockIdx.x; t < n_tiles; t += gridDim.x) {
        const int base = t * 64;
        for (int idx = tid; idx < 64 * 16; idx += NTHREADS) {
            const int i = idx >> 4;
            const int q = idx & 15;
            const int s = base + i;
            float4 v = make_float4(0.f, 0.f, 0.f, 0.f);
            if (s < N_NODES) v = reinterpret_cast<const float4*>(g_h + s * SD)[q];
            // xs stride 128: pack 64 inputs into first half of each row
            reinterpret_cast<float4*>(sm + R_XS + i * 128)[q] = v;
        }
        __syncthreads();

        gemm_tile64< 128, 64, true>(tid, sm + R_XS, sm + R_W1, b1, sm + R_H1);
        __syncthreads();
        // layer2 reads h1 (stride 128), writes into xs
        gemm_tile64<128, 128, true>(tid, sm + R_H1, sm + R_W2, b2, sm + R_XS);
        __syncthreads();

        // final 128 -> 2
        if (tid < 128) {
            const int i = tid >> 1;
            const int j = tid & 1;
            float acc = __ldg(b3 + j);
#pragma unroll 4
            for (int k = 0; k < 128; ++k)
                acc += sm[R_XS + i * 128 + k] * sm[R_W3 + j * 128 + k];
            sm[R_LG + i * 2 + j] = acc;
        }
        __syncthreads();

        if (tid < 64) {
            const int s = base + tid;
            if (s < N_NODES) {
                const float l0 = sm[R_LG + tid * 2];
                const float l1 = sm[R_LG + tid * 2 + 1];
                const float m  = fmaxf(l0, l1);
                const float e0 = __expf(l0 - m);
                const float e1 = __expf(l1 - m);
                const float inv = 1.0f / (e0 + e1);
                out[s * 2]     = e0 * inv;
                out[s * 2 + 1] = e1 * inv;
            }
        }
        __syncthreads();
    }
}

// ---------------------------------------------------------------------------
extern "C" void kernel_launch(void* const* d_in, const int* in_sizes, int n_in,
                              void* d_out, int out_size) {
    const int*   row   = (const int*)  d_in[0];
    const int*   col   = (const int*)  d_in[1];
    const float* eattr = (const float*)d_in[2];
    const float* mp_w1 = (const float*)d_in[5];
    const float* mp_b1 = (const float*)d_in[6];
    const float* mp_w2 = (const float*)d_in[7];
    const float* mp_b2 = (const float*)d_in[8];
    const float* mp_w3 = (const float*)d_in[9];
    const float* mp_b3 = (const float*)d_in[10];
    const float* w_ih  = (const float*)d_in[11];
    const float* w_hh  = (const float*)d_in[12];
    const float* b_ih  = (const float*)d_in[13];
    const float* b_hh  = (const float*)d_in[14];
    const float* ro_w1 = (const float*)d_in[15];
    const float* ro_b1 = (const float*)d_in[16];
    const float* ro_w2 = (const float*)d_in[17];
    const float* ro_b2 = (const float*)d_in[18];
    const float* ro_w3 = (const float*)d_in[19];
    const float* ro_b3 = (const float*)d_in[20];
    float* out = (float*)d_out;

    cudaFuncSetAttribute(k_edge,    cudaFuncAttributeMaxDynamicSharedMemorySize, E_SMEM_BYTES);
    cudaFuncSetAttribute(k_lstm,    cudaFuncAttributeMaxDynamicSharedMemorySize, L_SMEM_BYTES);
    cudaFuncSetAttribute(k_readout, cudaFuncAttributeMaxDynamicSharedMemorySize, R_SMEM_BYTES);

    k_init<<<(N_SEGS * SD + 255) / 256, 256>>>();

    for (int step = 0; step < N_STEPS; ++step) {
        k_edge<<<NBLK, NTHREADS, E_SMEM_BYTES>>>(row, col, eattr,
                                                 mp_w1, mp_b1, mp_w2, mp_b2, mp_w3, mp_b3);
        k_lstm<<<NBLK, NTHREADS, L_SMEM_BYTES>>>(w_ih, w_hh, b_ih, b_hh);
    }

    k_readout<<<NBLK, NTHREADS, R_SMEM_BYTES>>>(ro_w1, ro_b1, ro_w2, ro_b2, ro_w3, ro_b3, out);
}

// round 4
// speedup vs baseline: 1.5431x; 1.0776x over previous
#include <cuda_runtime.h>
#include <cuda_bf16.h>

// ---------------------------------------------------------------------------
// VGNN sparse GNN. Round 4: tensor-core (mma.sync tf32) GEMMs with hi/lo
// 3-MMA split for fp32-grade accuracy. Fused persistent tiles, XOR-swizzled
// smem, factor messages via direct stores (atomics only for node targets).
// ---------------------------------------------------------------------------

#define N_NODES   10000
#define N_FACTORS 20000
#define N_SEGS    30000
#define N_EDGES   80000
#define SD        64
#define N_STEPS   10
#define NT        256
#define NBLK      148

__device__ float g_h [N_SEGS * SD];
__device__ float g_c [N_SEGS * SD];
__device__ float g_nm[N_NODES * SD];     // node-targeted messages (atomics)
__device__ float g_f1[N_FACTORS * SD];   // factor messages, quarter 1 (col=f)
__device__ float g_f2[N_FACTORS * SD];   // factor messages, quarter 2 (col=f)

__device__ __forceinline__ float fsigmoid(float x) {
    return 1.0f / (1.0f + __expf(-x));
}
__device__ __forceinline__ float ftanh(float x) {
    return 2.0f * fsigmoid(2.0f * x) - 1.0f;
}

// ---------------------------------------------------------------------------
// tf32 helpers + mma.sync
// ---------------------------------------------------------------------------
__device__ __forceinline__ unsigned tf32_of(float x) {
    unsigned r;
    asm("cvt.rna.tf32.f32 %0, %1;" : "=r"(r) : "f"(x));
    return r;
}
__device__ __forceinline__ void split2(float x, unsigned& hi, unsigned& lo) {
    hi = tf32_of(x);
    lo = tf32_of(x - __uint_as_float(hi));
}
__device__ __forceinline__ void mma8(float (&d)[4],
                                     unsigned a0, unsigned a1, unsigned a2, unsigned a3,
                                     unsigned b0, unsigned b1) {
    asm volatile(
        "mma.sync.aligned.m16n8k8.row.col.f32.tf32.tf32.f32 "
        "{%0,%1,%2,%3},{%4,%5,%6,%7},{%8,%9},{%0,%1,%2,%3};"
        : "+f"(d[0]), "+f"(d[1]), "+f"(d[2]), "+f"(d[3])
        : "r"(a0), "r"(a1), "r"(a2), "r"(a3), "r"(b0), "r"(b1));
}

// Swizzled address: elem (row, k) of a [rows][STRIDE] buffer lives at
//   row*STRIDE + (k ^ ((row&7)<<2)).
// For all MMA fragment rows, row&7 == lane>>2, so sw is per-lane uniform.

// K-loop: d += A[m0:m0+16, 0:8*KSTEPS] * W[nbase+j*8+.., :]^T  (3-MMA tf32 split)
template <int NSUB, int KSTEPS>
__device__ __forceinline__ void mma_kloop(int lane, int m0, int nbase,
                                          const float* __restrict__ As,
                                          const float* __restrict__ Ws,
                                          float (&d)[NSUB][4]) {
    const int g  = lane >> 2;
    const int t  = lane & 3;
    const int sw = g << 2;
    const float* Ar0 = As + (m0 + g) * 128;
    const float* Ar1 = As + (m0 + 8 + g) * 128;
#pragma unroll 2
    for (int ks = 0; ks < KSTEPS; ++ks) {
        const int k0 = ks * 8;
        unsigned ah[4], al[4];
        split2(Ar0[(k0 + t)     ^ sw], ah[0], al[0]);
        split2(Ar1[(k0 + t)     ^ sw], ah[1], al[1]);
        split2(Ar0[(k0 + 4 + t) ^ sw], ah[2], al[2]);
        split2(Ar1[(k0 + 4 + t) ^ sw], ah[3], al[3]);
#pragma unroll
        for (int j = 0; j < NSUB; ++j) {
            const float* Wr = Ws + (nbase + j * 8 + g) * 128;
            unsigned bh0, bl0, bh1, bl1;
            split2(Wr[(k0 + t)     ^ sw], bh0, bl0);
            split2(Wr[(k0 + 4 + t) ^ sw], bh1, bl1);
            mma8(d[j], ah[0], ah[1], ah[2], ah[3], bh0, bh1);
            mma8(d[j], ah[0], ah[1], ah[2], ah[3], bl0, bl1);
            mma8(d[j], al[0], al[1], al[2], al[3], bh0, bh1);
        }
    }
}

// Store fragments (+bias, optional second bias, optional relu) to swizzled buf.
template <int NSUB, int STRIDE, bool RELU, bool BIAS2>
__device__ __forceinline__ void store_frags(int lane, int m0, int nbase,
                                            float (&d)[NSUB][4],
                                            float* __restrict__ Out,
                                            const float* __restrict__ bias_g,
                                            const float* __restrict__ bias_g2) {
    const int g  = lane >> 2;
    const int t  = lane & 3;
    const int sw = g << 2;
    float* O0 = Out + (m0 + g) * STRIDE;
    float* O1 = Out + (m0 + 8 + g) * STRIDE;
#pragma unroll
    for (int j = 0; j < NSUB; ++j) {
        const int c = nbase + j * 8 + 2 * t;
        float bx = __ldg(bias_g + c);
        float by = __ldg(bias_g + c + 1);
        if (BIAS2) { bx += __ldg(bias_g2 + c); by += __ldg(bias_g2 + c + 1); }
        float v0 = d[j][0] + bx, v1 = d[j][1] + by;
        float v2 = d[j][2] + bx, v3 = d[j][3] + by;
        if (RELU) {
            v0 = fmaxf(v0, 0.f); v1 = fmaxf(v1, 0.f);
            v2 = fmaxf(v2, 0.f); v3 = fmaxf(v3, 0.f);
        }
        const int cc = c ^ sw;
        *reinterpret_cast<float2*>(O0 + cc) = make_float2(v0, v1);
        *reinterpret_cast<float2*>(O1 + cc) = make_float2(v2, v3);
    }
}

// ---------------------------------------------------------------------------
// Edge kernel.  smem (floats):
//   W1s [128][128] swz   (w1 cols 0..127)
//   W1a [128][4]         (w1 cols 128..131 = attr weights)
//   W2s [128][128] swz
//   W3s [ 64][128] swz
//   XS  [ 64][128] swz   gather buf (h[row]|h[col]) -> layer2 out
//   H1  [ 64][128] swz   layer1 out -> msg [64][64] swz
// ---------------------------------------------------------------------------
#define EW1  0
#define EW1A (EW1 + 128 * 128)
#define EW2  (EW1A + 128 * 4)
#define EW3  (EW2 + 128 * 128)
#define EXS  (EW3 + 64 * 128)
#define EH1  (EXS + 64 * 128)
#define E_SMEM_BYTES ((EH1 + 64 * 128) * 4)   // 231424

__global__ void __launch_bounds__(NT, 1)
k_edge(const int* __restrict__ row, const int* __restrict__ col,
       const float* __restrict__ eattr,
       const float* __restrict__ w1, const float* __restrict__ b1,
       const float* __restrict__ w2, const float* __restrict__ b2,
       const float* __restrict__ w3, const float* __restrict__ b3) {
    extern __shared__ float sm[];
    const int tid  = threadIdx.x;
    const int wid  = tid >> 5;
    const int lane = tid & 31;

    // weight loads (swizzled by output row n)
    for (int idx = tid; idx < 128 * 128; idx += NT) {
        const int n = idx >> 7, k = idx & 127;
        const int swn = (n & 7) << 2;
        sm[EW1 + n * 128 + (k ^ swn)] = w1[n * 132 + k];
        sm[EW2 + n * 128 + (k ^ swn)] = w2[n * 128 + k];
    }
    for (int idx = tid; idx < 128 * 4; idx += NT) {
        sm[EW1A + idx] = w1[(idx >> 2) * 132 + 128 + (idx & 3)];
    }
    for (int idx = tid; idx < 64 * 128; idx += NT) {
        const int n = idx >> 7, k = idx & 127;
        sm[EW3 + n * 128 + (k ^ ((n & 7) << 2))] = w3[n * 128 + k];
    }
    __syncthreads();

    const int g = lane >> 2, t = lane & 3;
    const int m0     = (wid & 3) * 16;
    const int nbase  = (wid >> 2) * 64;   // layers 1,2 (N=128)
    const int nbase3 = (wid >> 2) * 32;   // layer 3   (N=64)

    const int n_tiles = N_EDGES / 64;  // 1250
    for (int tt = blockIdx.x; tt < n_tiles; tt += gridDim.x) {
        const int base = tt * 64;

        // gather xs = [h[row] | h[col]]  (swizzled float4 stores)
        for (int idx = tid; idx < 64 * 32; idx += NT) {
            const int i = idx >> 5;
            const int q = idx & 31;
            const int c = q * 4;
            const int e = base + i;
            const float4 v = (q < 16)
                ? __ldg(reinterpret_cast<const float4*>(g_h + __ldg(row + e) * SD) + q)
                : __ldg(reinterpret_cast<const float4*>(g_h + __ldg(col + e) * SD) + (q - 16));
            *reinterpret_cast<float4*>(sm + EXS + i * 128 + (c ^ ((i & 7) << 2))) = v;
        }
        __syncthreads();

        // ---- layer 1 ----
        {
            float d[8][4];
            // init with attr contribution (exact fp32)
            const float4 ar0 = __ldg(reinterpret_cast<const float4*>(eattr) + (base + m0 + g));
            const float4 ar1 = __ldg(reinterpret_cast<const float4*>(eattr) + (base + m0 + 8 + g));
#pragma unroll
            for (int j = 0; j < 8; ++j) {
                const int c = nbase + j * 8 + 2 * t;
                const float4 wA = *reinterpret_cast<const float4*>(sm + EW1A + c * 4);
                const float4 wB = *reinterpret_cast<const float4*>(sm + EW1A + (c + 1) * 4);
                d[j][0] = ar0.x * wA.x + ar0.y * wA.y + ar0.z * wA.z + ar0.w * wA.w;
                d[j][1] = ar0.x * wB.x + ar0.y * wB.y + ar0.z * wB.z + ar0.w * wB.w;
                d[j][2] = ar1.x * wA.x + ar1.y * wA.y + ar1.z * wA.z + ar1.w * wA.w;
                d[j][3] = ar1.x * wB.x + ar1.y * wB.y + ar1.z * wB.z + ar1.w * wB.w;
            }
            mma_kloop<8, 16>(lane, m0, nbase, sm + EXS, sm + EW1, d);
            store_frags<8, 128, true, false>(lane, m0, nbase, d, sm + EH1, b1, nullptr);
        }
        __syncthreads();

        // ---- layer 2: h1 -> xs ----
        {
            float d[8][4];
#pragma unroll
            for (int j = 0; j < 8; ++j) { d[j][0] = d[j][1] = d[j][2] = d[j][3] = 0.f; }
            mma_kloop<8, 16>(lane, m0, nbase, sm + EH1, sm + EW2, d);
            store_frags<8, 128, true, false>(lane, m0, nbase, d, sm + EXS, b2, nullptr);
        }
        __syncthreads();

        // ---- layer 3: xs -> msg (in H1 region, stride 64) ----
        {
            float d[4][4];
#pragma unroll
            for (int j = 0; j < 4; ++j) { d[j][0] = d[j][1] = d[j][2] = d[j][3] = 0.f; }
            mma_kloop<4, 16>(lane, m0, nbase3, sm + EXS, sm + EW3, d);
            store_frags<4, 64, false, false>(lane, m0, nbase3, d, sm + EH1, b3, nullptr);
        }
        __syncthreads();

        // scatter: factors -> direct stores, nodes -> atomics
        for (int idx = tid; idx < 64 * 64; idx += NT) {
            const int i  = idx >> 6;
            const int dd = idx & 63;
            const int e  = base + i;
            const float v = sm[EH1 + i * 64 + (dd ^ ((i & 7) << 2))];
            if (e < 20000) {
                g_f1[e * SD + dd] = v;
            } else if (e < 40000) {
                g_f2[(e - 20000) * SD + dd] = v;
            } else {
                atomicAdd(&g_nm[__ldg(col + e) * SD + dd], v);
            }
        }
        __syncthreads();
    }
}

// ---------------------------------------------------------------------------
// LSTM kernel.  A = [nm | h]  (32 segs x 128), B = [w_ih ; w_hh] (256 x 128).
// smem: WC [256][128] swz, AS [32][128] swz, GT [32][256] swz
// ---------------------------------------------------------------------------
#define LWC 0
#define LAS (LWC + 256 * 128)
#define LGT (LAS + 32 * 128)
#define L_SMEM_BYTES ((LGT + 32 * 256) * 4)   // 180224

__global__ void __launch_bounds__(NT, 1)
k_lstm(const float* __restrict__ wih, const float* __restrict__ whh,
       const float* __restrict__ bih, const float* __restrict__ bhh) {
    extern __shared__ float sm[];
    const int tid  = threadIdx.x;
    const int wid  = tid >> 5;
    const int lane = tid & 31;

    for (int idx = tid; idx < 256 * 128; idx += NT) {
        const int n = idx >> 7, k = idx & 127;
        const float v = (k < 64) ? wih[n * 64 + k] : whh[n * 64 + (k - 64)];
        sm[LWC + n * 128 + (k ^ ((n & 7) << 2))] = v;
    }
    __syncthreads();

    const int m0    = (wid & 1) * 16;
    const int nbase = (wid >> 1) * 64;

    const int n_tiles = (N_SEGS + 31) / 32;  // 938
    for (int tt = blockIdx.x; tt < n_tiles; tt += gridDim.x) {
        const int base = tt * 32;

        // gather A = [nm | h]
        for (int idx = tid; idx < 32 * 32; idx += NT) {
            const int i = idx >> 5;
            const int q = idx & 31;
            const int c = q * 4;
            const int s = base + i;
            float4 v = make_float4(0.f, 0.f, 0.f, 0.f);
            if (s < N_SEGS) {
                if (q < 16) {
                    if (s < N_NODES) {
                        v = reinterpret_cast<const float4*>(g_nm + s * SD)[q];
                    } else {
                        const int f = s - N_NODES;
                        const float4 a = reinterpret_cast<const float4*>(g_f1 + f * SD)[q];
                        const float4 b = reinterpret_cast<const float4*>(g_f2 + f * SD)[q];
                        v = make_float4(a.x + b.x, a.y + b.y, a.z + b.z, a.w + b.w);
                    }
                } else {
                    v = reinterpret_cast<const float4*>(g_h + s * SD)[q - 16];
                }
            }
            *reinterpret_cast<float4*>(sm + LAS + i * 128 + (c ^ ((i & 7) << 2))) = v;
        }
        __syncthreads();

        // gates = A * [Wih;Whh]^T + b_ih + b_hh
        {
            float d[8][4];
#pragma unroll
            for (int j = 0; j < 8; ++j) { d[j][0] = d[j][1] = d[j][2] = d[j][3] = 0.f; }
            mma_kloop<8, 16>(lane, m0, nbase, sm + LAS, sm + LWC, d);
            store_frags<8, 256, false, true>(lane, m0, nbase, d, sm + LGT, bih, bhh);
        }
        __syncthreads();

        // elementwise update + zero node nm
        for (int idx = tid; idx < 32 * 64; idx += NT) {
            const int i  = idx >> 6;
            const int dd = idx & 63;
            const int s  = base + i;
            if (s < N_SEGS) {
                const int o  = dd ^ ((i & 7) << 2);
                const float gi = sm[LGT + i * 256 + o];
                const float gf = sm[LGT + i * 256 + 64 + o];
                const float gg = sm[LGT + i * 256 + 128 + o];
                const float go = sm[LGT + i * 256 + 192 + o];
                const float cold = g_c[s * SD + dd];
                const float cn = fsigmoid(gf) * cold + fsigmoid(gi) * ftanh(gg);
                const float hn = fsigmoid(go) * ftanh(cn);
                g_c[s * SD + dd] = cn;
                g_h[s * SD + dd] = hn;
                if (s < N_NODES) g_nm[s * SD + dd] = 0.0f;
            }
        }
        __syncthreads();
    }
}

// ---------------------------------------------------------------------------
__global__ void k_init() {
    int idx = blockIdx.x * blockDim.x + threadIdx.x;
    if (idx >= N_SEGS * SD) return;
    int s = idx >> 6;
    int d = idx & 63;
    g_h[idx] = (s >= N_NODES && d == 0) ? 1.0f : 0.0f;
    g_c[idx] = 0.0f;
    if (s < N_NODES) g_nm[idx] = 0.0f;
}

// ---------------------------------------------------------------------------
// Readout (fp32 SIMT, runs once): h[:10000] -> 128 relu -> 128 relu -> 2 -> softmax
// ---------------------------------------------------------------------------
__device__ __forceinline__ void load_wT(int tid, const float* __restrict__ W,
                                        float* __restrict__ wT,
                                        int N, int K, int WS) {
    for (int idx = tid; idx < N * K; idx += NT) {
        int o = idx / K;
        int k = idx - o * K;
        wT[k * WS + o] = W[idx];
    }
}

template <int N, int K, bool RELU>
__device__ __forceinline__ void gemm_tile64(int tid,
                                            const float* __restrict__ xs,
                                            const float* __restrict__ wT,
                                            const float* __restrict__ bias_g,
                                            float* __restrict__ out) {
    constexpr int OG  = N / 4;
    constexpr int RG  = NT / OG;
    constexpr int EPT = 64 / RG;
    const int oo = tid % OG;
    const int eo = tid / OG;
    const int o  = oo * 4;
    const int e0 = eo * EPT;

    float acc[EPT][4];
    const float4 b4 = __ldg(reinterpret_cast<const float4*>(bias_g) + oo);
#pragma unroll
    for (int ii = 0; ii < EPT; ++ii) {
        acc[ii][0] = b4.x; acc[ii][1] = b4.y; acc[ii][2] = b4.z; acc[ii][3] = b4.w;
    }
#pragma unroll 4
    for (int k = 0; k < K; k += 4) {
        const float4 w0 = *reinterpret_cast<const float4*>(wT + (k + 0) * N + o);
        const float4 w1 = *reinterpret_cast<const float4*>(wT + (k + 1) * N + o);
        const float4 w2 = *reinterpret_cast<const float4*>(wT + (k + 2) * N + o);
        const float4 w3 = *reinterpret_cast<const float4*>(wT + (k + 3) * N + o);
#pragma unroll
        for (int ii = 0; ii < EPT; ++ii) {
            const float4 x4 = *reinterpret_cast<const float4*>(xs + (e0 + ii) * 128 + k);
            acc[ii][0] += x4.x * w0.x + x4.y * w1.x + x4.z * w2.x + x4.w * w3.x;
            acc[ii][1] += x4.x * w0.y + x4.y * w1.y + x4.z * w2.y + x4.w * w3.y;
            acc[ii][2] += x4.x * w0.z + x4.y * w1.z + x4.z * w2.z + x4.w * w3.z;
            acc[ii][3] += x4.x * w0.w + x4.y * w1.w + x4.z * w2.w + x4.w * w3.w;
        }
    }
#pragma unroll
    for (int ii = 0; ii < EPT; ++ii) {
        float4 r;
        r.x = acc[ii][0]; r.y = acc[ii][1]; r.z = acc[ii][2]; r.w = acc[ii][3];
        if (RELU) {
            r.x = fmaxf(r.x, 0.f); r.y = fmaxf(r.y, 0.f);
            r.z = fmaxf(r.z, 0.f); r.w = fmaxf(r.w, 0.f);
        }
        *reinterpret_cast<float4*>(out + (e0 + ii) * N + o) = r;
    }
}

#define R_W1 0
#define R_W2 (R_W1 + 64 * 128)
#define R_W3 (R_W2 + 128 * 128)
#define R_XS (R_W3 + 256)
#define R_H1 (R_XS + 64 * 128)
#define R_LG (R_H1 + 64 * 128)
#define R_SMEM_BYTES ((R_LG + 128) * 4)

__global__ void __launch_bounds__(NT, 1)
k_readout(const float* __restrict__ w1, const float* __restrict__ b1,
          const float* __restrict__ w2, const float* __restrict__ b2,
          const float* __restrict__ w3, const float* __restrict__ b3,
          float* __restrict__ out) {
    extern __shared__ float sm[];
    const int tid = threadIdx.x;

    load_wT(tid, w1, sm + R_W1, 128, 64, 128);
    load_wT(tid, w2, sm + R_W2, 128, 128, 128);
    for (int i = tid; i < 256; i += NT) sm[R_W3 + i] = w3[i];
    __syncthreads();

    const int n_tiles = (N_NODES + 63) / 64;  // 157
    for (int t = blockIdx.x; t < n_tiles; t += gridDim.x) {
        const int base = t * 64;
        for (int idx = tid; idx < 64 * 16; idx += NT) {
            const int i = idx >> 4;
            const int q = idx & 15;
            const int s = base + i;
            float4 v = make_float4(0.f, 0.f, 0.f, 0.f);
            if (s < N_NODES) v = reinterpret_cast<const float4*>(g_h + s * SD)[q];
            reinterpret_cast<float4*>(sm + R_XS + i * 128)[q] = v;
        }
        __syncthreads();

        gemm_tile64<128, 64, true>(tid, sm + R_XS, sm + R_W1, b1, sm + R_H1);
        __syncthreads();
        gemm_tile64<128, 128, true>(tid, sm + R_H1, sm + R_W2, b2, sm + R_XS);
        __syncthreads();

        if (tid < 128) {
            const int i = tid >> 1;
            const int j = tid & 1;
            float acc = __ldg(b3 + j);
#pragma unroll 4
            for (int k = 0; k < 128; ++k)
                acc += sm[R_XS + i * 128 + k] * sm[R_W3 + j * 128 + k];
            sm[R_LG + i * 2 + j] = acc;
        }
        __syncthreads();

        if (tid < 64) {
            const int s = base + tid;
            if (s < N_NODES) {
                const float l0 = sm[R_LG + tid * 2];
                const float l1 = sm[R_LG + tid * 2 + 1];
                const float m  = fmaxf(l0, l1);
                const float e0 = __expf(l0 - m);
                const float e1 = __expf(l1 - m);
                const float inv = 1.0f / (e0 + e1);
                out[s * 2]     = e0 * inv;
                out[s * 2 + 1] = e1 * inv;
            }
        }
        __syncthreads();
    }
}

// ---------------------------------------------------------------------------
extern "C" void kernel_launch(void* const* d_in, const int* in_sizes, int n_in,
                              void* d_out, int out_size) {
    const int*   row   = (const int*)  d_in[0];
    const int*   col   = (const int*)  d_in[1];
    const float* eattr = (const float*)d_in[2];
    const float* mp_w1 = (const float*)d_in[5];
    const float* mp_b1 = (const float*)d_in[6];
    const float* mp_w2 = (const float*)d_in[7];
    const float* mp_b2 = (const float*)d_in[8];
    const float* mp_w3 = (const float*)d_in[9];
    const float* mp_b3 = (const float*)d_in[10];
    const float* w_ih  = (const float*)d_in[11];
    const float* w_hh  = (const float*)d_in[12];
    const float* b_ih  = (const float*)d_in[13];
    const float* b_hh  = (const float*)d_in[14];
    const float* ro_w1 = (const float*)d_in[15];
    const float* ro_b1 = (const float*)d_in[16];
    const float* ro_w2 = (const float*)d_in[17];
    const float* ro_b2 = (const float*)d_in[18];
    const float* ro_w3 = (const float*)d_in[19];
    const float* ro_b3 = (const float*)d_in[20];
    float* out = (float*)d_out;

    cudaFuncSetAttribute(k_edge,    cudaFuncAttributeMaxDynamicSharedMemorySize, E_SMEM_BYTES);
    cudaFuncSetAttribute(k_lstm,    cudaFuncAttributeMaxDynamicSharedMemorySize, L_SMEM_BYTES);
    cudaFuncSetAttribute(k_readout, cudaFuncAttributeMaxDynamicSharedMemorySize, R_SMEM_BYTES);

    k_init<<<(N_SEGS * SD + 255) / 256, 256>>>();

    for (int step = 0; step < N_STEPS; ++step) {
        k_edge<<<NBLK, NT, E_SMEM_BYTES>>>(row, col, eattr,
                                           mp_w1, mp_b1, mp_w2, mp_b2, mp_w3, mp_b3);
        k_lstm<<<NBLK, NT, L_SMEM_BYTES>>>(w_ih, w_hh, b_ih, b_hh);
    }

    k_readout<<<NBLK, NT, R_SMEM_BYTES>>>(ro_w1, ro_b1, ro_w2, ro_b2, ro_w3, ro_b3, out);
}

// round 5
// speedup vs baseline: 3.1356x; 2.0320x over previous
#include <cuda_runtime.h>
#include <cuda_bf16.h>

// ---------------------------------------------------------------------------
// VGNN sparse GNN. Round 5: bf16 hi/lo split (2-way, 3-MMA) tensor-core GEMMs.
// All operands pre-split into separate hi/lo bf16 smem arrays (same bytes as
// fp32). Inner loop = ldmatrix.x4 + mma.m16n8k16.bf16 only. 512 thr/CTA.
// ---------------------------------------------------------------------------

#define N_NODES   10000
#define N_FACTORS 20000
#define N_SEGS    30000
#define N_EDGES   80000
#define SD        64
#define N_STEPS   10
#define NTE       512
#define NTL       512
#define NT_RO     256
#define NBLK      148

__device__ float g_h [N_SEGS * SD];
__device__ float g_c [N_SEGS * SD];
__device__ float g_nm[N_NODES * SD];     // node-targeted messages (atomics)
__device__ float g_f1[N_FACTORS * SD];   // factor messages, edges [0,20000)
__device__ float g_f2[N_FACTORS * SD];   // factor messages, edges [20000,40000)

__device__ __forceinline__ float fsigmoid(float x) {
    return 1.0f / (1.0f + __expf(-x));
}
__device__ __forceinline__ float ftanh(float x) {
    return 2.0f * fsigmoid(2.0f * x) - 1.0f;
}

__device__ __forceinline__ unsigned su32(const void* p) {
    return (unsigned)__cvta_generic_to_shared(p);
}

#define LDSM4(r0, r1, r2, r3, addr)                                          \
    asm volatile("ldmatrix.sync.aligned.m8n8.x4.shared.b16 {%0,%1,%2,%3},[%4];" \
                 : "=r"(r0), "=r"(r1), "=r"(r2), "=r"(r3) : "r"(addr))

__device__ __forceinline__ void mma16(float (&d)[4],
                                      unsigned a0, unsigned a1, unsigned a2, unsigned a3,
                                      unsigned b0, unsigned b1) {
    asm volatile(
        "mma.sync.aligned.m16n8k16.row.col.f32.bf16.bf16.f32 "
        "{%0,%1,%2,%3},{%4,%5,%6,%7},{%8,%9},{%0,%1,%2,%3};"
        : "+f"(d[0]), "+f"(d[1]), "+f"(d[2]), "+f"(d[3])
        : "r"(a0), "r"(a1), "r"(a2), "r"(a3), "r"(b0), "r"(b1));
}

// split (v0,v1) -> packed bf16x2 hi word (lo16=v0) and lo (residual) word
__device__ __forceinline__ void split_pack(float v0, float v1,
                                           unsigned& hw, unsigned& lw) {
    asm("cvt.rn.bf16x2.f32 %0, %1, %2;" : "=r"(hw) : "f"(v1), "f"(v0));
    const float h0 = __uint_as_float(hw << 16);
    const float h1 = __uint_as_float(hw & 0xffff0000u);
    const float r0 = v0 - h0;
    const float r1 = v1 - h1;
    asm("cvt.rn.bf16x2.f32 %0, %1, %2;" : "=r"(lw) : "f"(r1), "f"(r0));
}

// ---------------------------------------------------------------------------
// bf16 arrays: [rows][128] bf16, 256 B/row = 64 words/row.
// word (row, w) at row*64 + (w ^ ((row&7)<<2)).   (LDSM-compatible swizzle)
//
// kloop: d[j] += A[m0:m0+16, :128] * B[nbase+8j : nbase+8j+8, :128]^T
//        via 3-MMA hi/lo split, K chunks of 16.
// ---------------------------------------------------------------------------
template <int NSUB>
__device__ __forceinline__ void kloop(int lane,
                                      unsigned Ahi, unsigned Alo,
                                      unsigned Bhi, unsigned Blo,
                                      int m0, int nbase,
                                      float (&d)[NSUB][4]) {
    const int l7 = lane & 7;
    const int sw = l7 << 2;
    const unsigned a_row = (unsigned)(m0 + ((lane >> 3) & 1) * 8 + l7) * 256;
    const int a_kadd = (lane >> 4) * 4;
    const int b_kadd = ((lane >> 3) & 1) * 4;
    constexpr int NP = NSUB / 2;
    unsigned b_row[NP];
#pragma unroll
    for (int p = 0; p < NP; ++p)
        b_row[p] = (unsigned)(nbase + p * 16 + (lane >> 4) * 8 + l7) * 256;

#pragma unroll
    for (int ch = 0; ch < 8; ++ch) {
        const unsigned aoff = a_row + ((unsigned)((ch * 8 + a_kadd) ^ sw) << 2);
        unsigned ah[4], al[4];
        LDSM4(ah[0], ah[1], ah[2], ah[3], Ahi + aoff);
        LDSM4(al[0], al[1], al[2], al[3], Alo + aoff);
        const unsigned bk = (unsigned)((ch * 8 + b_kadd) ^ sw) << 2;
#pragma unroll
        for (int p = 0; p < NP; ++p) {
            unsigned bh[4], bl[4];
            LDSM4(bh[0], bh[1], bh[2], bh[3], Bhi + b_row[p] + bk);
            LDSM4(bl[0], bl[1], bl[2], bl[3], Blo + b_row[p] + bk);
            mma16(d[2 * p],     ah[0], ah[1], ah[2], ah[3], bh[0], bh[1]);
            mma16(d[2 * p],     ah[0], ah[1], ah[2], ah[3], bl[0], bl[1]);
            mma16(d[2 * p],     al[0], al[1], al[2], al[3], bh[0], bh[1]);
            mma16(d[2 * p + 1], ah[0], ah[1], ah[2], ah[3], bh[2], bh[3]);
            mma16(d[2 * p + 1], ah[0], ah[1], ah[2], ah[3], bl[2], bl[3]);
            mma16(d[2 * p + 1], al[0], al[1], al[2], al[3], bh[2], bh[3]);
        }
    }
}

// epilogue: +bias, relu, split to hi/lo bf16 arrays (pitch 64 words)
template <int NSUB, bool RELU>
__device__ __forceinline__ void store_split(int lane, int m0, int nbase,
                                            float (&d)[NSUB][4],
                                            unsigned* __restrict__ OutHi,
                                            unsigned* __restrict__ OutLo,
                                            const float* __restrict__ bias) {
    const int g = lane >> 2, t = lane & 3;
    const int sw = g << 2;
    unsigned* oh0 = OutHi + (m0 + g) * 64;
    unsigned* oh1 = OutHi + (m0 + 8 + g) * 64;
    unsigned* ol0 = OutLo + (m0 + g) * 64;
    unsigned* ol1 = OutLo + (m0 + 8 + g) * 64;
#pragma unroll
    for (int j = 0; j < NSUB; ++j) {
        const int c = nbase + j * 8 + 2 * t;
        const float bx = __ldg(bias + c);
        const float by = __ldg(bias + c + 1);
        float v0 = d[j][0] + bx, v1 = d[j][1] + by;
        float v2 = d[j][2] + bx, v3 = d[j][3] + by;
        if (RELU) {
            v0 = fmaxf(v0, 0.f); v1 = fmaxf(v1, 0.f);
            v2 = fmaxf(v2, 0.f); v3 = fmaxf(v3, 0.f);
        }
        unsigned hw0, lw0, hw1, lw1;
        split_pack(v0, v1, hw0, lw0);
        split_pack(v2, v3, hw1, lw1);
        const int wq = (c >> 1) ^ sw;
        oh0[wq] = hw0; ol0[wq] = lw0;
        oh1[wq] = hw1; ol1[wq] = lw1;
    }
}

// ---------------------------------------------------------------------------
// Edge kernel smem layout (byte offsets):
// ---------------------------------------------------------------------------
#define W1H 0
#define W1L (W1H + 32768)
#define W2H (W1L + 32768)
#define W2L (W2H + 32768)
#define W3H (W2L + 32768)
#define W3L (W3H + 16384)
#define XSH (W3L + 16384)
#define XSL (XSH + 16384)
#define H1H (XSL + 16384)           // layer-1 out; reused as fp32 msg [64][64]
#define H1L (H1H + 16384)
#define W1A (H1L + 16384)           // fp32 [128][4]
#define E_SMEM_BYTES (W1A + 2048)   // 231424 <= 232448

__global__ void __launch_bounds__(NTE, 1)
k_edge(const int* __restrict__ row, const int* __restrict__ col,
       const float* __restrict__ eattr,
       const float* __restrict__ w1, const float* __restrict__ b1,
       const float* __restrict__ w2, const float* __restrict__ b2,
       const float* __restrict__ w3, const float* __restrict__ b3) {
    extern __shared__ char smc[];
    const int tid = threadIdx.x, wid = tid >> 5, lane = tid & 31;

    unsigned* w1hp = (unsigned*)(smc + W1H);
    unsigned* w1lp = (unsigned*)(smc + W1L);
    unsigned* w2hp = (unsigned*)(smc + W2H);
    unsigned* w2lp = (unsigned*)(smc + W2L);
    unsigned* w3hp = (unsigned*)(smc + W3H);
    unsigned* w3lp = (unsigned*)(smc + W3L);
    unsigned* xshp = (unsigned*)(smc + XSH);
    unsigned* xslp = (unsigned*)(smc + XSL);
    unsigned* h1hp = (unsigned*)(smc + H1H);
    unsigned* h1lp = (unsigned*)(smc + H1L);
    float*    w1a  = (float*)(smc + W1A);
    float*    msg  = (float*)(smc + H1H);

    // ---- weight pre-split ----
    for (int idx = tid; idx < 128 * 64; idx += NTE) {
        const int n = idx >> 6, wq = idx & 63, k = wq * 2;
        const int off = n * 64 + (wq ^ ((n & 7) << 2));
        unsigned hw, lw;
        split_pack(w1[n * 132 + k], w1[n * 132 + k + 1], hw, lw);
        w1hp[off] = hw; w1lp[off] = lw;
        split_pack(w2[n * 128 + k], w2[n * 128 + k + 1], hw, lw);
        w2hp[off] = hw; w2lp[off] = lw;
    }
    for (int idx = tid; idx < 64 * 64; idx += NTE) {
        const int n = idx >> 6, wq = idx & 63, k = wq * 2;
        const int off = n * 64 + (wq ^ ((n & 7) << 2));
        unsigned hw, lw;
        split_pack(w3[n * 128 + k], w3[n * 128 + k + 1], hw, lw);
        w3hp[off] = hw; w3lp[off] = lw;
    }
    for (int idx = tid; idx < 512; idx += NTE)
        w1a[idx] = w1[(idx >> 2) * 132 + 128 + (idx & 3)];
    __syncthreads();

    const int g = lane >> 2, t = lane & 3;
    const int m0  = (wid & 3) * 16;
    const int nb2 = (wid >> 2) * 32;   // layers 1,2 (N=128)
    const int nb3 = (wid >> 2) * 16;   // layer 3   (N=64)

    const unsigned uXSH = su32(smc + XSH), uXSL = su32(smc + XSL);
    const unsigned uH1H = su32(smc + H1H), uH1L = su32(smc + H1L);
    const unsigned uW1H = su32(smc + W1H), uW1L = su32(smc + W1L);
    const unsigned uW2H = su32(smc + W2H), uW2L = su32(smc + W2L);
    const unsigned uW3H = su32(smc + W3H), uW3L = su32(smc + W3L);

    const int n_tiles = N_EDGES / 64;  // 1250
    for (int tt = blockIdx.x; tt < n_tiles; tt += gridDim.x) {
        const int base = tt * 64;

        // ---- gather xs = split([h[row] | h[col]]) ----
        for (int idx = tid; idx < 64 * 32; idx += NTE) {
            const int i = idx >> 5;
            const int q = idx & 31;
            const int e = base + i;
            const float4 v = (q < 16)
                ? __ldg(reinterpret_cast<const float4*>(g_h + __ldg(row + e) * SD) + q)
                : __ldg(reinterpret_cast<const float4*>(g_h + __ldg(col + e) * SD) + (q - 16));
            unsigned h0, l0, h1, l1;
            split_pack(v.x, v.y, h0, l0);
            split_pack(v.z, v.w, h1, l1);
            const int off = i * 64 + ((q * 2) ^ ((i & 7) << 2));
            *reinterpret_cast<uint2*>(xshp + off) = make_uint2(h0, h1);
            *reinterpret_cast<uint2*>(xslp + off) = make_uint2(l0, l1);
        }
        __syncthreads();

        // ---- layer 1: XS -> H1 (attr folded into init, exact fp32) ----
        {
            float d[4][4];
            const float4 ar0 = __ldg(reinterpret_cast<const float4*>(eattr) + (base + m0 + g));
            const float4 ar1 = __ldg(reinterpret_cast<const float4*>(eattr) + (base + m0 + 8 + g));
#pragma unroll
            for (int j = 0; j < 4; ++j) {
                const int c = nb2 + j * 8 + 2 * t;
                const float4 wA = *reinterpret_cast<const float4*>(w1a + c * 4);
                const float4 wB = *reinterpret_cast<const float4*>(w1a + (c + 1) * 4);
                d[j][0] = ar0.x * wA.x + ar0.y * wA.y + ar0.z * wA.z + ar0.w * wA.w;
                d[j][1] = ar0.x * wB.x + ar0.y * wB.y + ar0.z * wB.z + ar0.w * wB.w;
                d[j][2] = ar1.x * wA.x + ar1.y * wA.y + ar1.z * wA.z + ar1.w * wA.w;
                d[j][3] = ar1.x * wB.x + ar1.y * wB.y + ar1.z * wB.z + ar1.w * wB.w;
            }
            kloop<4>(lane, uXSH, uXSL, uW1H, uW1L, m0, nb2, d);
            store_split<4, true>(lane, m0, nb2, d, h1hp, h1lp, b1);
        }
        __syncthreads();

        // ---- layer 2: H1 -> XS ----
        {
            float d[4][4];
#pragma unroll
            for (int j = 0; j < 4; ++j) { d[j][0] = d[j][1] = d[j][2] = d[j][3] = 0.f; }
            kloop<4>(lane, uH1H, uH1L, uW2H, uW2L, m0, nb2, d);
            store_split<4, true>(lane, m0, nb2, d, xshp, xslp, b2);
        }
        __syncthreads();

        // ---- layer 3: XS -> msg (fp32, in H1 region, pitch 64) ----
        {
            float d[2][4];
#pragma unroll
            for (int j = 0; j < 2; ++j) { d[j][0] = d[j][1] = d[j][2] = d[j][3] = 0.f; }
            kloop<2>(lane, uXSH, uXSL, uW3H, uW3L, m0, nb3, d);
            const int sw = g << 2;
#pragma unroll
            for (int j = 0; j < 2; ++j) {
                const int c = nb3 + j * 8 + 2 * t;
                const float bx = __ldg(b3 + c);
                const float by = __ldg(b3 + c + 1);
                const int cc = c ^ sw;
                *reinterpret_cast<float2*>(msg + (m0 + g) * 64 + cc) =
                    make_float2(d[j][0] + bx, d[j][1] + by);
                *reinterpret_cast<float2*>(msg + (m0 + 8 + g) * 64 + cc) =
                    make_float2(d[j][2] + bx, d[j][3] + by);
            }
        }
        __syncthreads();

        // ---- scatter: factors -> direct stores, nodes -> atomics ----
        for (int idx = tid; idx < 64 * 64; idx += NTE) {
            const int i  = idx >> 6;
            const int dd = idx & 63;
            const int e  = base + i;
            const float v = msg[i * 64 + (dd ^ ((i & 7) << 2))];
            if (e < 20000) {
                g_f1[e * SD + dd] = v;
            } else if (e < 40000) {
                g_f2[(e - 20000) * SD + dd] = v;
            } else {
                atomicAdd(&g_nm[__ldg(col + e) * SD + dd], v);
            }
        }
        __syncthreads();
    }
}

// ---------------------------------------------------------------------------
// LSTM kernel. A = [nm|h] (32x128), B = [Wih;Whh] (256x128). bf16 split.
// ---------------------------------------------------------------------------
#define LWCH 0
#define LWCL (LWCH + 65536)
#define LASH (LWCL + 65536)
#define LASL (LASH + 8192)
#define LGT  (LASL + 8192)           // fp32 [32][256]
#define L_SMEM_BYTES (LGT + 32768)   // 180224

__global__ void __launch_bounds__(NTL, 1)
k_lstm(const float* __restrict__ wih, const float* __restrict__ whh,
       const float* __restrict__ bih, const float* __restrict__ bhh) {
    extern __shared__ char smc[];
    const int tid = threadIdx.x, wid = tid >> 5, lane = tid & 31;

    unsigned* wch = (unsigned*)(smc + LWCH);
    unsigned* wcl = (unsigned*)(smc + LWCL);
    unsigned* ash = (unsigned*)(smc + LASH);
    unsigned* asl = (unsigned*)(smc + LASL);
    float*    gt  = (float*)(smc + LGT);

    for (int idx = tid; idx < 256 * 64; idx += NTL) {
        const int n = idx >> 6, wq = idx & 63, k = wq * 2;
        const float v0 = (k < 64) ? wih[n * 64 + k]     : whh[n * 64 + (k - 64)];
        const float v1 = (k < 64) ? wih[n * 64 + k + 1] : whh[n * 64 + (k - 63)];
        unsigned hw, lw;
        split_pack(v0, v1, hw, lw);
        const int off = n * 64 + (wq ^ ((n & 7) << 2));
        wch[off] = hw; wcl[off] = lw;
    }
    __syncthreads();

    const int g = lane >> 2, t = lane & 3;
    const int m0 = (wid & 1) * 16;
    const int nb = (wid >> 1) * 32;

    const unsigned uASH = su32(smc + LASH), uASL = su32(smc + LASL);
    const unsigned uWCH = su32(smc + LWCH), uWCL = su32(smc + LWCL);

    const int n_tiles = (N_SEGS + 31) / 32;  // 938
    for (int tt = blockIdx.x; tt < n_tiles; tt += gridDim.x) {
        const int base = tt * 32;

        // gather A = split([nm | h])
        for (int idx = tid; idx < 32 * 32; idx += NTL) {
            const int i = idx >> 5;
            const int q = idx & 31;
            const int s = base + i;
            float4 v = make_float4(0.f, 0.f, 0.f, 0.f);
            if (s < N_SEGS) {
                if (q < 16) {
                    if (s < N_NODES) {
                        v = reinterpret_cast<const float4*>(g_nm + s * SD)[q];
                    } else {
                        const int f = s - N_NODES;
                        const float4 a = reinterpret_cast<const float4*>(g_f1 + f * SD)[q];
                        const float4 b = reinterpret_cast<const float4*>(g_f2 + f * SD)[q];
                        v = make_float4(a.x + b.x, a.y + b.y, a.z + b.z, a.w + b.w);
                    }
                } else {
                    v = reinterpret_cast<const float4*>(g_h + s * SD)[q - 16];
                }
            }
            unsigned h0, l0, h1, l1;
            split_pack(v.x, v.y, h0, l0);
            split_pack(v.z, v.w, h1, l1);
            const int off = i * 64 + ((q * 2) ^ ((i & 7) << 2));
            *reinterpret_cast<uint2*>(ash + off) = make_uint2(h0, h1);
            *reinterpret_cast<uint2*>(asl + off) = make_uint2(l0, l1);
        }
        __syncthreads();

        // gates = A * [Wih;Whh]^T + b_ih + b_hh   (fp32 out, pitch 256)
        {
            float d[4][4];
#pragma unroll
            for (int j = 0; j < 4; ++j) { d[j][0] = d[j][1] = d[j][2] = d[j][3] = 0.f; }
            kloop<4>(lane, uASH, uASL, uWCH, uWCL, m0, nb, d);
            const int sw = g << 2;
#pragma unroll
            for (int j = 0; j < 4; ++j) {
                const int c = nb + j * 8 + 2 * t;
                const float bx = __ldg(bih + c) + __ldg(bhh + c);
                const float by = __ldg(bih + c + 1) + __ldg(bhh + c + 1);
                const int cc = c ^ sw;
                *reinterpret_cast<float2*>(gt + (m0 + g) * 256 + cc) =
                    make_float2(d[j][0] + bx, d[j][1] + by);
                *reinterpret_cast<float2*>(gt + (m0 + 8 + g) * 256 + cc) =
                    make_float2(d[j][2] + bx, d[j][3] + by);
            }
        }
        __syncthreads();

        // elementwise LSTM update + zero node nm
        for (int idx = tid; idx < 32 * 64; idx += NTL) {
            const int i  = idx >> 6;
            const int dd = idx & 63;
            const int s  = base + i;
            if (s < N_SEGS) {
                const int o = dd ^ ((i & 7) << 2);
                const float gi = gt[i * 256 + o];
                const float gf = gt[i * 256 + 64 + o];
                const float gg = gt[i * 256 + 128 + o];
                const float go = gt[i * 256 + 192 + o];
                const float cold = g_c[s * SD + dd];
                const float cn = fsigmoid(gf) * cold + fsigmoid(gi) * ftanh(gg);
                const float hn = fsigmoid(go) * ftanh(cn);
                g_c[s * SD + dd] = cn;
                g_h[s * SD + dd] = hn;
                if (s < N_NODES) g_nm[s * SD + dd] = 0.0f;
            }
        }
        __syncthreads();
    }
}

// ---------------------------------------------------------------------------
__global__ void k_init() {
    int idx = blockIdx.x * blockDim.x + threadIdx.x;
    if (idx >= N_SEGS * SD) return;
    int s = idx >> 6;
    int d = idx & 63;
    g_h[idx] = (s >= N_NODES && d == 0) ? 1.0f : 0.0f;
    g_c[idx] = 0.0f;
    if (s < N_NODES) g_nm[idx] = 0.0f;
}

// ---------------------------------------------------------------------------
// Readout (fp32 SIMT, runs once)
// ---------------------------------------------------------------------------
__device__ __forceinline__ void load_wT(int tid, const float* __restrict__ W,
                                        float* __restrict__ wT,
                                        int N, int K, int WS) {
    for (int idx = tid; idx < N * K; idx += NT_RO) {
        int o = idx / K;
        int k = idx - o * K;
        wT[k * WS + o] = W[idx];
    }
}

template <int N, int K, bool RELU>
__device__ __forceinline__ void gemm_tile64(int tid,
                                            const float* __restrict__ xs,
                                            const float* __restrict__ wT,
                                            const float* __restrict__ bias_g,
                                            float* __restrict__ out) {
    constexpr int OG  = N / 4;
    constexpr int RG  = NT_RO / OG;
    constexpr int EPT = 64 / RG;
    const int oo = tid % OG;
    const int eo = tid / OG;
    const int o  = oo * 4;
    const int e0 = eo * EPT;

    float acc[EPT][4];
    const float4 b4 = __ldg(reinterpret_cast<const float4*>(bias_g) + oo);
#pragma unroll
    for (int ii = 0; ii < EPT; ++ii) {
        acc[ii][0] = b4.x; acc[ii][1] = b4.y; acc[ii][2] = b4.z; acc[ii][3] = b4.w;
    }
#pragma unroll 4
    for (int k = 0; k < K; k += 4) {
        const float4 w0 = *reinterpret_cast<const float4*>(wT + (k + 0) * N + o);
        const float4 w1 = *reinterpret_cast<const float4*>(wT + (k + 1) * N + o);
        const float4 w2 = *reinterpret_cast<const float4*>(wT + (k + 2) * N + o);
        const float4 w3 = *reinterpret_cast<const float4*>(wT + (k + 3) * N + o);
#pragma unroll
        for (int ii = 0; ii < EPT; ++ii) {
            const float4 x4 = *reinterpret_cast<const float4*>(xs + (e0 + ii) * 128 + k);
            acc[ii][0] += x4.x * w0.x + x4.y * w1.x + x4.z * w2.x + x4.w * w3.x;
            acc[ii][1] += x4.x * w0.y + x4.y * w1.y + x4.z * w2.y + x4.w * w3.y;
            acc[ii][2] += x4.x * w0.z + x4.y * w1.z + x4.z * w2.z + x4.w * w3.z;
            acc[ii][3] += x4.x * w0.w + x4.y * w1.w + x4.z * w2.w + x4.w * w3.w;
        }
    }
#pragma unroll
    for (int ii = 0; ii < EPT; ++ii) {
        float4 r;
        r.x = acc[ii][0]; r.y = acc[ii][1]; r.z = acc[ii][2]; r.w = acc[ii][3];
        if (RELU) {
            r.x = fmaxf(r.x, 0.f); r.y = fmaxf(r.y, 0.f);
            r.z = fmaxf(r.z, 0.f); r.w = fmaxf(r.w, 0.f);
        }
        *reinterpret_cast<float4*>(out + (e0 + ii) * N + o) = r;
    }
}

#define R_W1 0
#define R_W2 (R_W1 + 64 * 128)
#define R_W3 (R_W2 + 128 * 128)
#define R_XS (R_W3 + 256)
#define R_H1 (R_XS + 64 * 128)
#define R_LG (R_H1 + 64 * 128)
#define R_SMEM_BYTES ((R_LG + 128) * 4)

__global__ void __launch_bounds__(NT_RO, 1)
k_readout(const float* __restrict__ w1, const float* __restrict__ b1,
          const float* __restrict__ w2, const float* __restrict__ b2,
          const float* __restrict__ w3, const float* __restrict__ b3,
          float* __restrict__ out) {
    extern __shared__ float smf[];
    const int tid = threadIdx.x;

    load_wT(tid, w1, smf + R_W1, 128, 64, 128);
    load_wT(tid, w2, smf + R_W2, 128, 128, 128);
    for (int i = tid; i < 256; i += NT_RO) smf[R_W3 + i] = w3[i];
    __syncthreads();

    const int n_tiles = (N_NODES + 63) / 64;  // 157
    for (int t = blockIdx.x; t < n_tiles; t += gridDim.x) {
        const int base = t * 64;
        for (int idx = tid; idx < 64 * 16; idx += NT_RO) {
            const int i = idx >> 4;
            const int q = idx & 15;
            const int s = base + i;
            float4 v = make_float4(0.f, 0.f, 0.f, 0.f);
            if (s < N_NODES) v = reinterpret_cast<const float4*>(g_h + s * SD)[q];
            reinterpret_cast<float4*>(smf + R_XS + i * 128)[q] = v;
        }
        __syncthreads();

        gemm_tile64<128, 64, true>(tid, smf + R_XS, smf + R_W1, b1, smf + R_H1);
        __syncthreads();
        gemm_tile64<128, 128, true>(tid, smf + R_H1, smf + R_W2, b2, smf + R_XS);
        __syncthreads();

        if (tid < 128) {
            const int i = tid >> 1;
            const int j = tid & 1;
            float acc = __ldg(b3 + j);
#pragma unroll 4
            for (int k = 0; k < 128; ++k)
                acc += smf[R_XS + i * 128 + k] * smf[R_W3 + j * 128 + k];
            smf[R_LG + i * 2 + j] = acc;
        }
        __syncthreads();

        if (tid < 64) {
            const int s = base + tid;
            if (s < N_NODES) {
                const float l0 = smf[R_LG + tid * 2];
                const float l1 = smf[R_LG + tid * 2 + 1];
                const float m  = fmaxf(l0, l1);
                const float e0 = __expf(l0 - m);
                const float e1 = __expf(l1 - m);
                const float inv = 1.0f / (e0 + e1);
                out[s * 2]     = e0 * inv;
                out[s * 2 + 1] = e1 * inv;
            }
        }
        __syncthreads();
    }
}

// ---------------------------------------------------------------------------
extern "C" void kernel_launch(void* const* d_in, const int* in_sizes, int n_in,
                              void* d_out, int out_size) {
    const int*   row   = (const int*)  d_in[0];
    const int*   col   = (const int*)  d_in[1];
    const float* eattr = (const float*)d_in[2];
    const float* mp_w1 = (const float*)d_in[5];
    const float* mp_b1 = (const float*)d_in[6];
    const float* mp_w2 = (const float*)d_in[7];
    const float* mp_b2 = (const float*)d_in[8];
    const float* mp_w3 = (const float*)d_in[9];
    const float* mp_b3 = (const float*)d_in[10];
    const float* w_ih  = (const float*)d_in[11];
    const float* w_hh  = (const float*)d_in[12];
    const float* b_ih  = (const float*)d_in[13];
    const float* b_hh  = (const float*)d_in[14];
    const float* ro_w1 = (const float*)d_in[15];
    const float* ro_b1 = (const float*)d_in[16];
    const float* ro_w2 = (const float*)d_in[17];
    const float* ro_b2 = (const float*)d_in[18];
    const float* ro_w3 = (const float*)d_in[19];
    const float* ro_b3 = (const float*)d_in[20];
    float* out = (float*)d_out;

    cudaFuncSetAttribute(k_edge,    cudaFuncAttributeMaxDynamicSharedMemorySize, E_SMEM_BYTES);
    cudaFuncSetAttribute(k_lstm,    cudaFuncAttributeMaxDynamicSharedMemorySize, L_SMEM_BYTES);
    cudaFuncSetAttribute(k_readout, cudaFuncAttributeMaxDynamicSharedMemorySize, R_SMEM_BYTES);

    k_init<<<(N_SEGS * SD + 255) / 256, 256>>>();

    for (int step = 0; step < N_STEPS; ++step) {
        k_edge<<<NBLK, NTE, E_SMEM_BYTES>>>(row, col, eattr,
                                            mp_w1, mp_b1, mp_w2, mp_b2, mp_w3, mp_b3);
        k_lstm<<<NBLK, NTL, L_SMEM_BYTES>>>(w_ih, w_hh, b_ih, b_hh);
    }

    k_readout<<<NBLK, NT_RO, R_SMEM_BYTES>>>(ro_w1, ro_b1, ro_w2, ro_b2, ro_w3, ro_b3, out);
}

// round 6
// speedup vs baseline: 3.5096x; 1.1193x over previous
#include <cuda_runtime.h>
#include <cuda_bf16.h>

// ---------------------------------------------------------------------------
// VGNN sparse GNN. Round 6: bf16 hi/lo split tensor-core GEMMs +
//  - register-prefetched gather (hides L2 latency across GEMM stages)
//  - layer-3 scatter directly from MMA accumulators (no msg smem, -2 barriers)
// ---------------------------------------------------------------------------

#define N_NODES   10000
#define N_FACTORS 20000
#define N_SEGS    30000
#define N_EDGES   80000
#define SD        64
#define N_STEPS   10
#define NTE       512
#define NTL       512
#define NT_RO     256
#define NBLK      148

__device__ float g_h [N_SEGS * SD];
__device__ float g_c [N_SEGS * SD];
__device__ float g_nm[N_NODES * SD];     // node-targeted messages (atomics)
__device__ float g_f1[N_FACTORS * SD];   // factor messages, edges [0,20000)
__device__ float g_f2[N_FACTORS * SD];   // factor messages, edges [20000,40000)

__device__ __forceinline__ float fsigmoid(float x) {
    return 1.0f / (1.0f + __expf(-x));
}
__device__ __forceinline__ float ftanh(float x) {
    return 2.0f * fsigmoid(2.0f * x) - 1.0f;
}

__device__ __forceinline__ unsigned su32(const void* p) {
    return (unsigned)__cvta_generic_to_shared(p);
}

#define LDSM4(r0, r1, r2, r3, addr)                                          \
    asm volatile("ldmatrix.sync.aligned.m8n8.x4.shared.b16 {%0,%1,%2,%3},[%4];" \
                 : "=r"(r0), "=r"(r1), "=r"(r2), "=r"(r3) : "r"(addr))

__device__ __forceinline__ void mma16(float (&d)[4],
                                      unsigned a0, unsigned a1, unsigned a2, unsigned a3,
                                      unsigned b0, unsigned b1) {
    asm volatile(
        "mma.sync.aligned.m16n8k16.row.col.f32.bf16.bf16.f32 "
        "{%0,%1,%2,%3},{%4,%5,%6,%7},{%8,%9},{%0,%1,%2,%3};"
        : "+f"(d[0]), "+f"(d[1]), "+f"(d[2]), "+f"(d[3])
        : "r"(a0), "r"(a1), "r"(a2), "r"(a3), "r"(b0), "r"(b1));
}

// split (v0,v1) -> packed bf16x2 hi word (lo16=v0) and lo (residual) word
__device__ __forceinline__ void split_pack(float v0, float v1,
                                           unsigned& hw, unsigned& lw) {
    asm("cvt.rn.bf16x2.f32 %0, %1, %2;" : "=r"(hw) : "f"(v1), "f"(v0));
    const float h0 = __uint_as_float(hw << 16);
    const float h1 = __uint_as_float(hw & 0xffff0000u);
    const float r0 = v0 - h0;
    const float r1 = v1 - h1;
    asm("cvt.rn.bf16x2.f32 %0, %1, %2;" : "=r"(lw) : "f"(r1), "f"(r0));
}

// ---------------------------------------------------------------------------
// bf16 arrays: [rows][128] bf16, 256 B/row = 64 words/row.
// word (row, w) at row*64 + (w ^ ((row&7)<<2)).   (LDSM-compatible swizzle)
// ---------------------------------------------------------------------------
template <int NSUB>
__device__ __forceinline__ void kloop(int lane,
                                      unsigned Ahi, unsigned Alo,
                                      unsigned Bhi, unsigned Blo,
                                      int m0, int nbase,
                                      float (&d)[NSUB][4]) {
    const int l7 = lane & 7;
    const int sw = l7 << 2;
    const unsigned a_row = (unsigned)(m0 + ((lane >> 3) & 1) * 8 + l7) * 256;
    const int a_kadd = (lane >> 4) * 4;
    const int b_kadd = ((lane >> 3) & 1) * 4;
    constexpr int NP = NSUB / 2;
    unsigned b_row[NP];
#pragma unroll
    for (int p = 0; p < NP; ++p)
        b_row[p] = (unsigned)(nbase + p * 16 + (lane >> 4) * 8 + l7) * 256;

#pragma unroll
    for (int ch = 0; ch < 8; ++ch) {
        const unsigned aoff = a_row + ((unsigned)((ch * 8 + a_kadd) ^ sw) << 2);
        unsigned ah[4], al[4];
        LDSM4(ah[0], ah[1], ah[2], ah[3], Ahi + aoff);
        LDSM4(al[0], al[1], al[2], al[3], Alo + aoff);
        const unsigned bk = (unsigned)((ch * 8 + b_kadd) ^ sw) << 2;
#pragma unroll
        for (int p = 0; p < NP; ++p) {
            unsigned bh[4], bl[4];
            LDSM4(bh[0], bh[1], bh[2], bh[3], Bhi + b_row[p] + bk);
            LDSM4(bl[0], bl[1], bl[2], bl[3], Blo + b_row[p] + bk);
            mma16(d[2 * p],     ah[0], ah[1], ah[2], ah[3], bh[0], bh[1]);
            mma16(d[2 * p],     ah[0], ah[1], ah[2], ah[3], bl[0], bl[1]);
            mma16(d[2 * p],     al[0], al[1], al[2], al[3], bh[0], bh[1]);
            mma16(d[2 * p + 1], ah[0], ah[1], ah[2], ah[3], bh[2], bh[3]);
            mma16(d[2 * p + 1], ah[0], ah[1], ah[2], ah[3], bl[2], bl[3]);
            mma16(d[2 * p + 1], al[0], al[1], al[2], al[3], bh[2], bh[3]);
        }
    }
}

// epilogue: +bias, relu, split to hi/lo bf16 arrays (pitch 64 words)
template <int NSUB, bool RELU>
__device__ __forceinline__ void store_split(int lane, int m0, int nbase,
                                            float (&d)[NSUB][4],
                                            unsigned* __restrict__ OutHi,
                                            unsigned* __restrict__ OutLo,
                                            const float* __restrict__ bias) {
    const int g = lane >> 2, t = lane & 3;
    const int sw = g << 2;
    unsigned* oh0 = OutHi + (m0 + g) * 64;
    unsigned* oh1 = OutHi + (m0 + 8 + g) * 64;
    unsigned* ol0 = OutLo + (m0 + g) * 64;
    unsigned* ol1 = OutLo + (m0 + 8 + g) * 64;
#pragma unroll
    for (int j = 0; j < NSUB; ++j) {
        const int c = nbase + j * 8 + 2 * t;
        const float bx = __ldg(bias + c);
        const float by = __ldg(bias + c + 1);
        float v0 = d[j][0] + bx, v1 = d[j][1] + by;
        float v2 = d[j][2] + bx, v3 = d[j][3] + by;
        if (RELU) {
            v0 = fmaxf(v0, 0.f); v1 = fmaxf(v1, 0.f);
            v2 = fmaxf(v2, 0.f); v3 = fmaxf(v3, 0.f);
        }
        unsigned hw0, lw0, hw1, lw1;
        split_pack(v0, v1, hw0, lw0);
        split_pack(v2, v3, hw1, lw1);
        const int wq = (c >> 1) ^ sw;
        oh0[wq] = hw0; ol0[wq] = lw0;
        oh1[wq] = hw1; ol1[wq] = lw1;
    }
}

// gather helpers ------------------------------------------------------------
__device__ __forceinline__ float4 gather_slot(const int* __restrict__ row,
                                              const int* __restrict__ col,
                                              int base, int idx) {
    const int i = idx >> 5, q = idx & 31;
    const int e = base + i;
    const int n = (q < 16) ? __ldg(row + e) : __ldg(col + e);
    const int qq = (q < 16) ? q : q - 16;
    return __ldg(reinterpret_cast<const float4*>(g_h + n * SD) + qq);
}

__device__ __forceinline__ void store_slot(unsigned* __restrict__ xsh,
                                           unsigned* __restrict__ xsl,
                                           int idx, float4 v) {
    const int i = idx >> 5, q = idx & 31;
    unsigned h0, l0, h1, l1;
    split_pack(v.x, v.y, h0, l0);
    split_pack(v.z, v.w, h1, l1);
    const int off = i * 64 + ((q * 2) ^ ((i & 7) << 2));
    *reinterpret_cast<uint2*>(xsh + off) = make_uint2(h0, h1);
    *reinterpret_cast<uint2*>(xsl + off) = make_uint2(l0, l1);
}

// direct message scatter from registers
__device__ __forceinline__ void scatter2(const int* __restrict__ col,
                                         int e, int c, float v0, float v1) {
    if (e < 20000) {
        *reinterpret_cast<float2*>(g_f1 + e * SD + c) = make_float2(v0, v1);
    } else if (e < 40000) {
        *reinterpret_cast<float2*>(g_f2 + (e - 20000) * SD + c) = make_float2(v0, v1);
    } else {
        const int s = __ldg(col + e);
        atomicAdd(g_nm + s * SD + c, v0);
        atomicAdd(g_nm + s * SD + c + 1, v1);
    }
}

// ---------------------------------------------------------------------------
// Edge kernel smem layout (byte offsets):
// ---------------------------------------------------------------------------
#define W1H 0
#define W1L (W1H + 32768)
#define W2H (W1L + 32768)
#define W2L (W2H + 32768)
#define W3H (W2L + 32768)
#define W3L (W3H + 16384)
#define XSH (W3L + 16384)
#define XSL (XSH + 16384)
#define H1H (XSL + 16384)
#define H1L (H1H + 16384)
#define W1A (H1L + 16384)           // fp32 [128][4]
#define E_SMEM_BYTES (W1A + 2048)   // 231424 <= 232448

__global__ void __launch_bounds__(NTE, 1)
k_edge(const int* __restrict__ row, const int* __restrict__ col,
       const float* __restrict__ eattr,
       const float* __restrict__ w1, const float* __restrict__ b1,
       const float* __restrict__ w2, const float* __restrict__ b2,
       const float* __restrict__ w3, const float* __restrict__ b3) {
    extern __shared__ char smc[];
    const int tid = threadIdx.x, wid = tid >> 5, lane = tid & 31;

    unsigned* w1hp = (unsigned*)(smc + W1H);
    unsigned* w1lp = (unsigned*)(smc + W1L);
    unsigned* w2hp = (unsigned*)(smc + W2H);
    unsigned* w2lp = (unsigned*)(smc + W2L);
    unsigned* w3hp = (unsigned*)(smc + W3H);
    unsigned* w3lp = (unsigned*)(smc + W3L);
    unsigned* xshp = (unsigned*)(smc + XSH);
    unsigned* xslp = (unsigned*)(smc + XSL);
    unsigned* h1hp = (unsigned*)(smc + H1H);
    unsigned* h1lp = (unsigned*)(smc + H1L);
    float*    w1a  = (float*)(smc + W1A);

    // ---- weight pre-split ----
    for (int idx = tid; idx < 128 * 64; idx += NTE) {
        const int n = idx >> 6, wq = idx & 63, k = wq * 2;
        const int off = n * 64 + (wq ^ ((n & 7) << 2));
        unsigned hw, lw;
        split_pack(w1[n * 132 + k], w1[n * 132 + k + 1], hw, lw);
        w1hp[off] = hw; w1lp[off] = lw;
        split_pack(w2[n * 128 + k], w2[n * 128 + k + 1], hw, lw);
        w2hp[off] = hw; w2lp[off] = lw;
    }
    for (int idx = tid; idx < 64 * 64; idx += NTE) {
        const int n = idx >> 6, wq = idx & 63, k = wq * 2;
        const int off = n * 64 + (wq ^ ((n & 7) << 2));
        unsigned hw, lw;
        split_pack(w3[n * 128 + k], w3[n * 128 + k + 1], hw, lw);
        w3hp[off] = hw; w3lp[off] = lw;
    }
    for (int idx = tid; idx < 512; idx += NTE)
        w1a[idx] = w1[(idx >> 2) * 132 + 128 + (idx & 3)];
    __syncthreads();

    const int g = lane >> 2, t = lane & 3;
    const int m0  = (wid & 3) * 16;
    const int nb2 = (wid >> 2) * 32;   // layers 1,2 (N=128)
    const int nb3 = (wid >> 2) * 16;   // layer 3   (N=64)

    const unsigned uXSH = su32(smc + XSH), uXSL = su32(smc + XSL);
    const unsigned uH1H = su32(smc + H1H), uH1L = su32(smc + H1L);
    const unsigned uW1H = su32(smc + W1H), uW1L = su32(smc + W1L);
    const unsigned uW2H = su32(smc + W2H), uW2L = su32(smc + W2L);
    const unsigned uW3H = su32(smc + W3H), uW3L = su32(smc + W3L);

    const int n_tiles = N_EDGES / 64;  // 1250

    // prefetch first tile's half-gather into registers
    int tt = blockIdx.x;
    float4 r0, r1;
    if (tt < n_tiles) {
        r0 = gather_slot(row, col, tt * 64, tid);
        r1 = gather_slot(row, col, tt * 64, tid + 512);
    }

    for (; tt < n_tiles; tt += gridDim.x) {
        const int base = tt * 64;

        // ---- populate XS: prefetched half + direct half ----
        {
            const float4 a = gather_slot(row, col, base, tid + 1024);
            const float4 b = gather_slot(row, col, base, tid + 1536);
            store_slot(xshp, xslp, tid, r0);
            store_slot(xshp, xslp, tid + 512, r1);
            store_slot(xshp, xslp, tid + 1024, a);
            store_slot(xshp, xslp, tid + 1536, b);
        }
        __syncthreads();

        // issue next tile's half-gather (lands during the 3 GEMM stages)
        const int ntt = tt + gridDim.x;
        if (ntt < n_tiles) {
            r0 = gather_slot(row, col, ntt * 64, tid);
            r1 = gather_slot(row, col, ntt * 64, tid + 512);
        }

        // ---- layer 1: XS -> H1 (attr folded into init, exact fp32) ----
        {
            float d[4][4];
            const float4 ar0 = __ldg(reinterpret_cast<const float4*>(eattr) + (base + m0 + g));
            const float4 ar1 = __ldg(reinterpret_cast<const float4*>(eattr) + (base + m0 + 8 + g));
#pragma unroll
            for (int j = 0; j < 4; ++j) {
                const int c = nb2 + j * 8 + 2 * t;
                const float4 wA = *reinterpret_cast<const float4*>(w1a + c * 4);
                const float4 wB = *reinterpret_cast<const float4*>(w1a + (c + 1) * 4);
                d[j][0] = ar0.x * wA.x + ar0.y * wA.y + ar0.z * wA.z + ar0.w * wA.w;
                d[j][1] = ar0.x * wB.x + ar0.y * wB.y + ar0.z * wB.z + ar0.w * wB.w;
                d[j][2] = ar1.x * wA.x + ar1.y * wA.y + ar1.z * wA.z + ar1.w * wA.w;
                d[j][3] = ar1.x * wB.x + ar1.y * wB.y + ar1.z * wB.z + ar1.w * wB.w;
            }
            kloop<4>(lane, uXSH, uXSL, uW1H, uW1L, m0, nb2, d);
            store_split<4, true>(lane, m0, nb2, d, h1hp, h1lp, b1);
        }
        __syncthreads();

        // ---- layer 2: H1 -> XS ----
        {
            float d[4][4];
#pragma unroll
            for (int j = 0; j < 4; ++j) { d[j][0] = d[j][1] = d[j][2] = d[j][3] = 0.f; }
            kloop<4>(lane, uH1H, uH1L, uW2H, uW2L, m0, nb2, d);
            store_split<4, true>(lane, m0, nb2, d, xshp, xslp, b2);
        }
        __syncthreads();

        // ---- layer 3: XS -> messages, scattered straight from registers ----
        {
            float d[2][4];
#pragma unroll
            for (int j = 0; j < 2; ++j) { d[j][0] = d[j][1] = d[j][2] = d[j][3] = 0.f; }
            kloop<2>(lane, uXSH, uXSL, uW3H, uW3L, m0, nb3, d);
            const int e0 = base + m0 + g;
            const int e1 = base + m0 + 8 + g;
#pragma unroll
            for (int j = 0; j < 2; ++j) {
                const int c = nb3 + j * 8 + 2 * t;
                const float bx = __ldg(b3 + c);
                const float by = __ldg(b3 + c + 1);
                scatter2(col, e0, c, d[j][0] + bx, d[j][1] + by);
                scatter2(col, e1, c, d[j][2] + bx, d[j][3] + by);
            }
        }
        __syncthreads();   // XS/H1 free for next tile
    }
}

// ---------------------------------------------------------------------------
// LSTM kernel. A = [nm|h] (32x128), B = [Wih;Whh] (256x128). bf16 split.
// ---------------------------------------------------------------------------
#define LWCH 0
#define LWCL (LWCH + 65536)
#define LASH (LWCL + 65536)
#define LASL (LASH + 8192)
#define LGT  (LASL + 8192)           // fp32 [32][256]
#define L_SMEM_BYTES (LGT + 32768)   // 180224

__global__ void __launch_bounds__(NTL, 1)
k_lstm(const float* __restrict__ wih, const float* __restrict__ whh,
       const float* __restrict__ bih, const float* __restrict__ bhh) {
    extern __shared__ char smc[];
    const int tid = threadIdx.x, wid = tid >> 5, lane = tid & 31;

    unsigned* wch = (unsigned*)(smc + LWCH);
    unsigned* wcl = (unsigned*)(smc + LWCL);
    unsigned* ash = (unsigned*)(smc + LASH);
    unsigned* asl = (unsigned*)(smc + LASL);
    float*    gt  = (float*)(smc + LGT);

    for (int idx = tid; idx < 256 * 64; idx += NTL) {
        const int n = idx >> 6, wq = idx & 63, k = wq * 2;
        const float v0 = (k < 64) ? wih[n * 64 + k]     : whh[n * 64 + (k - 64)];
        const float v1 = (k < 64) ? wih[n * 64 + k + 1] : whh[n * 64 + (k - 63)];
        unsigned hw, lw;
        split_pack(v0, v1, hw, lw);
        const int off = n * 64 + (wq ^ ((n & 7) << 2));
        wch[off] = hw; wcl[off] = lw;
    }
    __syncthreads();

    const int g = lane >> 2, t = lane & 3;
    const int m0 = (wid & 1) * 16;
    const int nb = (wid >> 1) * 32;

    const unsigned uASH = su32(smc + LASH), uASL = su32(smc + LASL);
    const unsigned uWCH = su32(smc + LWCH), uWCL = su32(smc + LWCL);

    const int n_tiles = (N_SEGS + 31) / 32;  // 938
    for (int tt = blockIdx.x; tt < n_tiles; tt += gridDim.x) {
        const int base = tt * 32;

        // gather A = split([nm | h])
        for (int idx = tid; idx < 32 * 32; idx += NTL) {
            const int i = idx >> 5;
            const int q = idx & 31;
            const int s = base + i;
            float4 v = make_float4(0.f, 0.f, 0.f, 0.f);
            if (s < N_SEGS) {
                if (q < 16) {
                    if (s < N_NODES) {
                        v = reinterpret_cast<const float4*>(g_nm + s * SD)[q];
                    } else {
                        const int f = s - N_NODES;
                        const float4 a = reinterpret_cast<const float4*>(g_f1 + f * SD)[q];
                        const float4 b = reinterpret_cast<const float4*>(g_f2 + f * SD)[q];
                        v = make_float4(a.x + b.x, a.y + b.y, a.z + b.z, a.w + b.w);
                    }
                } else {
                    v = reinterpret_cast<const float4*>(g_h + s * SD)[q - 16];
                }
            }
            unsigned h0, l0, h1, l1;
            split_pack(v.x, v.y, h0, l0);
            split_pack(v.z, v.w, h1, l1);
            const int off = i * 64 + ((q * 2) ^ ((i & 7) << 2));
            *reinterpret_cast<uint2*>(ash + off) = make_uint2(h0, h1);
            *reinterpret_cast<uint2*>(asl + off) = make_uint2(l0, l1);
        }
        __syncthreads();

        // gates = A * [Wih;Whh]^T + b_ih + b_hh   (fp32 out, pitch 256)
        {
            float d[4][4];
#pragma unroll
            for (int j = 0; j < 4; ++j) { d[j][0] = d[j][1] = d[j][2] = d[j][3] = 0.f; }
            kloop<4>(lane, uASH, uASL, uWCH, uWCL, m0, nb, d);
            const int sw = g << 2;
#pragma unroll
            for (int j = 0; j < 4; ++j) {
                const int c = nb + j * 8 + 2 * t;
                const float bx = __ldg(bih + c) + __ldg(bhh + c);
                const float by = __ldg(bih + c + 1) + __ldg(bhh + c + 1);
                const int cc = c ^ sw;
                *reinterpret_cast<float2*>(gt + (m0 + g) * 256 + cc) =
                    make_float2(d[j][0] + bx, d[j][1] + by);
                *reinterpret_cast<float2*>(gt + (m0 + 8 + g) * 256 + cc) =
                    make_float2(d[j][2] + bx, d[j][3] + by);
            }
        }
        __syncthreads();

        // elementwise LSTM update + zero node nm
        for (int idx = tid; idx < 32 * 64; idx += NTL) {
            const int i  = idx >> 6;
            const int dd = idx & 63;
            const int s  = base + i;
            if (s < N_SEGS) {
                const int o = dd ^ ((i & 7) << 2);
                const float gi = gt[i * 256 + o];
                const float gf = gt[i * 256 + 64 + o];
                const float gg = gt[i * 256 + 128 + o];
                const float go = gt[i * 256 + 192 + o];
                const float cold = g_c[s * SD + dd];
                const float cn = fsigmoid(gf) * cold + fsigmoid(gi) * ftanh(gg);
                const float hn = fsigmoid(go) * ftanh(cn);
                g_c[s * SD + dd] = cn;
                g_h[s * SD + dd] = hn;
                if (s < N_NODES) g_nm[s * SD + dd] = 0.0f;
            }
        }
        __syncthreads();
    }
}

// ---------------------------------------------------------------------------
__global__ void k_init() {
    int idx = blockIdx.x * blockDim.x + threadIdx.x;
    if (idx >= N_SEGS * SD) return;
    int s = idx >> 6;
    int d = idx & 63;
    g_h[idx] = (s >= N_NODES && d == 0) ? 1.0f : 0.0f;
    g_c[idx] = 0.0f;
    if (s < N_NODES) g_nm[idx] = 0.0f;
}

// ---------------------------------------------------------------------------
// Readout (fp32 SIMT, runs once)
// ---------------------------------------------------------------------------
__device__ __forceinline__ void load_wT(int tid, const float* __restrict__ W,
                                        float* __restrict__ wT,
                                        int N, int K, int WS) {
    for (int idx = tid; idx < N * K; idx += NT_RO) {
        int o = idx / K;
        int k = idx - o * K;
        wT[k * WS + o] = W[idx];
    }
}

template <int N, int K, bool RELU>
__device__ __forceinline__ void gemm_tile64(int tid,
                                            const float* __restrict__ xs,
                                            const float* __restrict__ wT,
                                            const float* __restrict__ bias_g,
                                            float* __restrict__ out) {
    constexpr int OG  = N / 4;
    constexpr int RG  = NT_RO / OG;
    constexpr int EPT = 64 / RG;
    const int oo = tid % OG;
    const int eo = tid / OG;
    const int o  = oo * 4;
    const int e0 = eo * EPT;

    float acc[EPT][4];
    const float4 b4 = __ldg(reinterpret_cast<const float4*>(bias_g) + oo);
#pragma unroll
    for (int ii = 0; ii < EPT; ++ii) {
        acc[ii][0] = b4.x; acc[ii][1] = b4.y; acc[ii][2] = b4.z; acc[ii][3] = b4.w;
    }
#pragma unroll 4
    for (int k = 0; k < K; k += 4) {
        const float4 w0 = *reinterpret_cast<const float4*>(wT + (k + 0) * N + o);
        const float4 w1 = *reinterpret_cast<const float4*>(wT + (k + 1) * N + o);
        const float4 w2 = *reinterpret_cast<const float4*>(wT + (k + 2) * N + o);
        const float4 w3 = *reinterpret_cast<const float4*>(wT + (k + 3) * N + o);
#pragma unroll
        for (int ii = 0; ii < EPT; ++ii) {
            const float4 x4 = *reinterpret_cast<const float4*>(xs + (e0 + ii) * 128 + k);
            acc[ii][0] += x4.x * w0.x + x4.y * w1.x + x4.z * w2.x + x4.w * w3.x;
            acc[ii][1] += x4.x * w0.y + x4.y * w1.y + x4.z * w2.y + x4.w * w3.y;
            acc[ii][2] += x4.x * w0.z + x4.y * w1.z + x4.z * w2.z + x4.w * w3.z;
            acc[ii][3] += x4.x * w0.w + x4.y * w1.w + x4.z * w2.w + x4.w * w3.w;
        }
    }
#pragma unroll
    for (int ii = 0; ii < EPT; ++ii) {
        float4 r;
        r.x = acc[ii][0]; r.y = acc[ii][1]; r.z = acc[ii][2]; r.w = acc[ii][3];
        if (RELU) {
            r.x = fmaxf(r.x, 0.f); r.y = fmaxf(r.y, 0.f);
            r.z = fmaxf(r.z, 0.f); r.w = fmaxf(r.w, 0.f);
        }
        *reinterpret_cast<float4*>(out + (e0 + ii) * N + o) = r;
    }
}

#define R_W1 0
#define R_W2 (R_W1 + 64 * 128)
#define R_W3 (R_W2 + 128 * 128)
#define R_XS (R_W3 + 256)
#define R_H1 (R_XS + 64 * 128)
#define R_LG (R_H1 + 64 * 128)
#define R_SMEM_BYTES ((R_LG + 128) * 4)

__global__ void __launch_bounds__(NT_RO, 1)
k_readout(const float* __restrict__ w1, const float* __restrict__ b1,
          const float* __restrict__ w2, const float* __restrict__ b2,
          const float* __restrict__ w3, const float* __restrict__ b3,
          float* __restrict__ out) {
    extern __shared__ float smf[];
    const int tid = threadIdx.x;

    load_wT(tid, w1, smf + R_W1, 128, 64, 128);
    load_wT(tid, w2, smf + R_W2, 128, 128, 128);
    for (int i = tid; i < 256; i += NT_RO) smf[R_W3 + i] = w3[i];
    __syncthreads();

    const int n_tiles = (N_NODES + 63) / 64;  // 157
    for (int t = blockIdx.x; t < n_tiles; t += gridDim.x) {
        const int base = t * 64;
        for (int idx = tid; idx < 64 * 16; idx += NT_RO) {
            const int i = idx >> 4;
            const int q = idx & 15;
            const int s = base + i;
            float4 v = make_float4(0.f, 0.f, 0.f, 0.f);
            if (s < N_NODES) v = reinterpret_cast<const float4*>(g_h + s * SD)[q];
            reinterpret_cast<float4*>(smf + R_XS + i * 128)[q] = v;
        }
        __syncthreads();

        gemm_tile64<128, 64, true>(tid, smf + R_XS, smf + R_W1, b1, smf + R_H1);
        __syncthreads();
        gemm_tile64<128, 128, true>(tid, smf + R_H1, smf + R_W2, b2, smf + R_XS);
        __syncthreads();

        if (tid < 128) {
            const int i = tid >> 1;
            const int j = tid & 1;
            float acc = __ldg(b3 + j);
#pragma unroll 4
            for (int k = 0; k < 128; ++k)
                acc += smf[R_XS + i * 128 + k] * smf[R_W3 + j * 128 + k];
            smf[R_LG + i * 2 + j] = acc;
        }
        __syncthreads();

        if (tid < 64) {
            const int s = base + tid;
            if (s < N_NODES) {
                const float l0 = smf[R_LG + tid * 2];
                const float l1 = smf[R_LG + tid * 2 + 1];
                const float m  = fmaxf(l0, l1);
                const float e0 = __expf(l0 - m);
                const float e1 = __expf(l1 - m);
                const float inv = 1.0f / (e0 + e1);
                out[s * 2]     = e0 * inv;
                out[s * 2 + 1] = e1 * inv;
            }
        }
        __syncthreads();
    }
}

// ---------------------------------------------------------------------------
extern "C" void kernel_launch(void* const* d_in, const int* in_sizes, int n_in,
                              void* d_out, int out_size) {
    const int*   row   = (const int*)  d_in[0];
    const int*   col   = (const int*)  d_in[1];
    const float* eattr = (const float*)d_in[2];
    const float* mp_w1 = (const float*)d_in[5];
    const float* mp_b1 = (const float*)d_in[6];
    const float* mp_w2 = (const float*)d_in[7];
    const float* mp_b2 = (const float*)d_in[8];
    const float* mp_w3 = (const float*)d_in[9];
    const float* mp_b3 = (const float*)d_in[10];
    const float* w_ih  = (const float*)d_in[11];
    const float* w_hh  = (const float*)d_in[12];
    const float* b_ih  = (const float*)d_in[13];
    const float* b_hh  = (const float*)d_in[14];
    const float* ro_w1 = (const float*)d_in[15];
    const float* ro_b1 = (const float*)d_in[16];
    const float* ro_w2 = (const float*)d_in[17];
    const float* ro_b2 = (const float*)d_in[18];
    const float* ro_w3 = (const float*)d_in[19];
    const float* ro_b3 = (const float*)d_in[20];
    float* out = (float*)d_out;

    cudaFuncSetAttribute(k_edge,    cudaFuncAttributeMaxDynamicSharedMemorySize, E_SMEM_BYTES);
    cudaFuncSetAttribute(k_lstm,    cudaFuncAttributeMaxDynamicSharedMemorySize, L_SMEM_BYTES);
    cudaFuncSetAttribute(k_readout, cudaFuncAttributeMaxDynamicSharedMemorySize, R_SMEM_BYTES);

    k_init<<<(N_SEGS * SD + 255) / 256, 256>>>();

    for (int step = 0; step < N_STEPS; ++step) {
        k_edge<<<NBLK, NTE, E_SMEM_BYTES>>>(row, col, eattr,
                                            mp_w1, mp_b1, mp_w2, mp_b2, mp_w3, mp_b3);
        k_lstm<<<NBLK, NTL, L_SMEM_BYTES>>>(w_ih, w_hh, b_ih, b_hh);
    }

    k_readout<<<NBLK, NT_RO, R_SMEM_BYTES>>>(ro_w1, ro_b1, ro_w2, ro_b2, ro_w3, ro_b3, out);
}

// round 7
// speedup vs baseline: 3.6048x; 1.0271x over previous
#include <cuda_runtime.h>
#include <cuda_bf16.h>

// ---------------------------------------------------------------------------
// VGNN sparse GNN. Round 7: bf16 hi/lo split MMA with interleaved accumulator
// chains (dep distance 1 -> 4), register-cached biases, prefetched gather,
// register scatter. Same math/order as Round 6 (bit-identical epilogues).
// ---------------------------------------------------------------------------

#define N_NODES   10000
#define N_FACTORS 20000
#define N_SEGS    30000
#define N_EDGES   80000
#define SD        64
#define N_STEPS   10
#define NTE       512
#define NTL       512
#define NT_RO     256
#define NBLK      148

__device__ float g_h [N_SEGS * SD];
__device__ float g_c [N_SEGS * SD];
__device__ float g_nm[N_NODES * SD];     // node-targeted messages (atomics)
__device__ float g_f1[N_FACTORS * SD];   // factor messages, edges [0,20000)
__device__ float g_f2[N_FACTORS * SD];   // factor messages, edges [20000,40000)

__device__ __forceinline__ float fsigmoid(float x) {
    return 1.0f / (1.0f + __expf(-x));
}
__device__ __forceinline__ float ftanh(float x) {
    return 2.0f * fsigmoid(2.0f * x) - 1.0f;
}

__device__ __forceinline__ unsigned su32(const void* p) {
    return (unsigned)__cvta_generic_to_shared(p);
}

#define LDSM4(r0, r1, r2, r3, addr)                                          \
    asm volatile("ldmatrix.sync.aligned.m8n8.x4.shared.b16 {%0,%1,%2,%3},[%4];" \
                 : "=r"(r0), "=r"(r1), "=r"(r2), "=r"(r3) : "r"(addr))

__device__ __forceinline__ void mma16(float (&d)[4],
                                      unsigned a0, unsigned a1, unsigned a2, unsigned a3,
                                      unsigned b0, unsigned b1) {
    asm volatile(
        "mma.sync.aligned.m16n8k16.row.col.f32.bf16.bf16.f32 "
        "{%0,%1,%2,%3},{%4,%5,%6,%7},{%8,%9},{%0,%1,%2,%3};"
        : "+f"(d[0]), "+f"(d[1]), "+f"(d[2]), "+f"(d[3])
        : "r"(a0), "r"(a1), "r"(a2), "r"(a3), "r"(b0), "r"(b1));
}

// split (v0,v1) -> packed bf16x2 hi word (lo16=v0) and lo (residual) word
__device__ __forceinline__ void split_pack(float v0, float v1,
                                           unsigned& hw, unsigned& lw) {
    asm("cvt.rn.bf16x2.f32 %0, %1, %2;" : "=r"(hw) : "f"(v1), "f"(v0));
    const float h0 = __uint_as_float(hw << 16);
    const float h1 = __uint_as_float(hw & 0xffff0000u);
    const float r0 = v0 - h0;
    const float r1 = v1 - h1;
    asm("cvt.rn.bf16x2.f32 %0, %1, %2;" : "=r"(lw) : "f"(r1), "f"(r0));
}

// ---------------------------------------------------------------------------
// bf16 arrays: [rows][128] bf16, 256 B/row = 64 words/row.
// word (row, w) at row*64 + (w ^ ((row&7)<<2)).   (LDSM-compatible swizzle)
//
// kloop: per chunk, ALL B fragments loaded first, then 3 passes of MMAs
// round-robin over the accumulators (dep distance NSUB instead of 1).
// Per-accumulator MMA order is unchanged vs previous rounds (hh, hl, lh).
// ---------------------------------------------------------------------------
template <int NSUB>
__device__ __forceinline__ void kloop(int lane,
                                      unsigned Ahi, unsigned Alo,
                                      unsigned Bhi, unsigned Blo,
                                      int m0, int nbase,
                                      float (&d)[NSUB][4]) {
    const int l7 = lane & 7;
    const int sw = l7 << 2;
    const unsigned a_row = (unsigned)(m0 + ((lane >> 3) & 1) * 8 + l7) * 256;
    const int a_kadd = (lane >> 4) * 4;
    const int b_kadd = ((lane >> 3) & 1) * 4;
    constexpr int NP = NSUB / 2;
    unsigned b_row[NP];
#pragma unroll
    for (int p = 0; p < NP; ++p)
        b_row[p] = (unsigned)(nbase + p * 16 + (lane >> 4) * 8 + l7) * 256;

#pragma unroll
    for (int ch = 0; ch < 8; ++ch) {
        const unsigned aoff = a_row + ((unsigned)((ch * 8 + a_kadd) ^ sw) << 2);
        unsigned ah[4], al[4];
        LDSM4(ah[0], ah[1], ah[2], ah[3], Ahi + aoff);
        LDSM4(al[0], al[1], al[2], al[3], Alo + aoff);
        const unsigned bk = (unsigned)((ch * 8 + b_kadd) ^ sw) << 2;
        unsigned bh[NP][4], bl[NP][4];
#pragma unroll
        for (int p = 0; p < NP; ++p) {
            LDSM4(bh[p][0], bh[p][1], bh[p][2], bh[p][3], Bhi + b_row[p] + bk);
            LDSM4(bl[p][0], bl[p][1], bl[p][2], bl[p][3], Blo + b_row[p] + bk);
        }
        // pass 1: ah * bh   (each accumulator touched once per pass)
#pragma unroll
        for (int p = 0; p < NP; ++p) {
            mma16(d[2 * p],     ah[0], ah[1], ah[2], ah[3], bh[p][0], bh[p][1]);
            mma16(d[2 * p + 1], ah[0], ah[1], ah[2], ah[3], bh[p][2], bh[p][3]);
        }
        // pass 2: ah * bl
#pragma unroll
        for (int p = 0; p < NP; ++p) {
            mma16(d[2 * p],     ah[0], ah[1], ah[2], ah[3], bl[p][0], bl[p][1]);
            mma16(d[2 * p + 1], ah[0], ah[1], ah[2], ah[3], bl[p][2], bl[p][3]);
        }
        // pass 3: al * bh
#pragma unroll
        for (int p = 0; p < NP; ++p) {
            mma16(d[2 * p],     al[0], al[1], al[2], al[3], bh[p][0], bh[p][1]);
            mma16(d[2 * p + 1], al[0], al[1], al[2], al[3], bh[p][2], bh[p][3]);
        }
    }
}

// epilogue: +cached bias, relu, split to hi/lo bf16 arrays (pitch 64 words)
template <int NSUB, bool RELU>
__device__ __forceinline__ void store_split(int lane, int m0, int nbase,
                                            float (&d)[NSUB][4],
                                            unsigned* __restrict__ OutHi,
                                            unsigned* __restrict__ OutLo,
                                            const float (&bc)[NSUB][2]) {
    const int g = lane >> 2, t = lane & 3;
    const int sw = g << 2;
    unsigned* oh0 = OutHi + (m0 + g) * 64;
    unsigned* oh1 = OutHi + (m0 + 8 + g) * 64;
    unsigned* ol0 = OutLo + (m0 + g) * 64;
    unsigned* ol1 = OutLo + (m0 + 8 + g) * 64;
#pragma unroll
    for (int j = 0; j < NSUB; ++j) {
        const int c = nbase + j * 8 + 2 * t;
        const float bx = bc[j][0];
        const float by = bc[j][1];
        float v0 = d[j][0] + bx, v1 = d[j][1] + by;
        float v2 = d[j][2] + bx, v3 = d[j][3] + by;
        if (RELU) {
            v0 = fmaxf(v0, 0.f); v1 = fmaxf(v1, 0.f);
            v2 = fmaxf(v2, 0.f); v3 = fmaxf(v3, 0.f);
        }
        unsigned hw0, lw0, hw1, lw1;
        split_pack(v0, v1, hw0, lw0);
        split_pack(v2, v3, hw1, lw1);
        const int wq = (c >> 1) ^ sw;
        oh0[wq] = hw0; ol0[wq] = lw0;
        oh1[wq] = hw1; ol1[wq] = lw1;
    }
}

// gather helpers ------------------------------------------------------------
__device__ __forceinline__ float4 gather_slot(const int* __restrict__ row,
                                              const int* __restrict__ col,
                                              int base, int idx) {
    const int i = idx >> 5, q = idx & 31;
    const int e = base + i;
    const int n = (q < 16) ? __ldg(row + e) : __ldg(col + e);
    const int qq = (q < 16) ? q : q - 16;
    return __ldg(reinterpret_cast<const float4*>(g_h + n * SD) + qq);
}

__device__ __forceinline__ void store_slot(unsigned* __restrict__ xsh,
                                           unsigned* __restrict__ xsl,
                                           int idx, float4 v) {
    const int i = idx >> 5, q = idx & 31;
    unsigned h0, l0, h1, l1;
    split_pack(v.x, v.y, h0, l0);
    split_pack(v.z, v.w, h1, l1);
    const int off = i * 64 + ((q * 2) ^ ((i & 7) << 2));
    *reinterpret_cast<uint2*>(xsh + off) = make_uint2(h0, h1);
    *reinterpret_cast<uint2*>(xsl + off) = make_uint2(l0, l1);
}

// direct message scatter from registers
__device__ __forceinline__ void scatter2(const int* __restrict__ col,
                                         int e, int c, float v0, float v1) {
    if (e < 20000) {
        *reinterpret_cast<float2*>(g_f1 + e * SD + c) = make_float2(v0, v1);
    } else if (e < 40000) {
        *reinterpret_cast<float2*>(g_f2 + (e - 20000) * SD + c) = make_float2(v0, v1);
    } else {
        const int s = __ldg(col + e);
        atomicAdd(g_nm + s * SD + c, v0);
        atomicAdd(g_nm + s * SD + c + 1, v1);
    }
}

// ---------------------------------------------------------------------------
// Edge kernel smem layout (byte offsets):
// ---------------------------------------------------------------------------
#define W1H 0
#define W1L (W1H + 32768)
#define W2H (W1L + 32768)
#define W2L (W2H + 32768)
#define W3H (W2L + 32768)
#define W3L (W3H + 16384)
#define XSH (W3L + 16384)
#define XSL (XSH + 16384)
#define H1H (XSL + 16384)
#define H1L (H1H + 16384)
#define W1A (H1L + 16384)           // fp32 [128][4]
#define E_SMEM_BYTES (W1A + 2048)   // 231424 <= 232448

__global__ void __launch_bounds__(NTE, 1)
k_edge(const int* __restrict__ row, const int* __restrict__ col,
       const float* __restrict__ eattr,
       const float* __restrict__ w1, const float* __restrict__ b1,
       const float* __restrict__ w2, const float* __restrict__ b2,
       const float* __restrict__ w3, const float* __restrict__ b3) {
    extern __shared__ char smc[];
    const int tid = threadIdx.x, wid = tid >> 5, lane = tid & 31;

    unsigned* w1hp = (unsigned*)(smc + W1H);
    unsigned* w1lp = (unsigned*)(smc + W1L);
    unsigned* w2hp = (unsigned*)(smc + W2H);
    unsigned* w2lp = (unsigned*)(smc + W2L);
    unsigned* w3hp = (unsigned*)(smc + W3H);
    unsigned* w3lp = (unsigned*)(smc + W3L);
    unsigned* xshp = (unsigned*)(smc + XSH);
    unsigned* xslp = (unsigned*)(smc + XSL);
    unsigned* h1hp = (unsigned*)(smc + H1H);
    unsigned* h1lp = (unsigned*)(smc + H1L);
    float*    w1a  = (float*)(smc + W1A);

    // ---- weight pre-split ----
    for (int idx = tid; idx < 128 * 64; idx += NTE) {
        const int n = idx >> 6, wq = idx & 63, k = wq * 2;
        const int off = n * 64 + (wq ^ ((n & 7) << 2));
        unsigned hw, lw;
        split_pack(w1[n * 132 + k], w1[n * 132 + k + 1], hw, lw);
        w1hp[off] = hw; w1lp[off] = lw;
        split_pack(w2[n * 128 + k], w2[n * 128 + k + 1], hw, lw);
        w2hp[off] = hw; w2lp[off] = lw;
    }
    for (int idx = tid; idx < 64 * 64; idx += NTE) {
        const int n = idx >> 6, wq = idx & 63, k = wq * 2;
        const int off = n * 64 + (wq ^ ((n & 7) << 2));
        unsigned hw, lw;
        split_pack(w3[n * 128 + k], w3[n * 128 + k + 1], hw, lw);
        w3hp[off] = hw; w3lp[off] = lw;
    }
    for (int idx = tid; idx < 512; idx += NTE)
        w1a[idx] = w1[(idx >> 2) * 132 + 128 + (idx & 3)];
    __syncthreads();

    const int g = lane >> 2, t = lane & 3;
    const int m0  = (wid & 3) * 16;
    const int nb2 = (wid >> 2) * 32;   // layers 1,2 (N=128)
    const int nb3 = (wid >> 2) * 16;   // layer 3   (N=64)

    // register-cached bias slices (loop-invariant)
    float b1c[4][2], b2c[4][2], b3c[2][2];
#pragma unroll
    for (int j = 0; j < 4; ++j) {
        b1c[j][0] = __ldg(b1 + nb2 + j * 8 + 2 * t);
        b1c[j][1] = __ldg(b1 + nb2 + j * 8 + 2 * t + 1);
        b2c[j][0] = __ldg(b2 + nb2 + j * 8 + 2 * t);
        b2c[j][1] = __ldg(b2 + nb2 + j * 8 + 2 * t + 1);
    }
#pragma unroll
    for (int j = 0; j < 2; ++j) {
        b3c[j][0] = __ldg(b3 + nb3 + j * 8 + 2 * t);
        b3c[j][1] = __ldg(b3 + nb3 + j * 8 + 2 * t + 1);
    }

    const unsigned uXSH = su32(smc + XSH), uXSL = su32(smc + XSL);
    const unsigned uH1H = su32(smc + H1H), uH1L = su32(smc + H1L);
    const unsigned uW1H = su32(smc + W1H), uW1L = su32(smc + W1L);
    const unsigned uW2H = su32(smc + W2H), uW2L = su32(smc + W2L);
    const unsigned uW3H = su32(smc + W3H), uW3L = su32(smc + W3L);

    const int n_tiles = N_EDGES / 64;  // 1250

    // prefetch first tile's half-gather into registers
    int tt = blockIdx.x;
    float4 r0, r1;
    if (tt < n_tiles) {
        r0 = gather_slot(row, col, tt * 64, tid);
        r1 = gather_slot(row, col, tt * 64, tid + 512);
    }

    for (; tt < n_tiles; tt += gridDim.x) {
        const int base = tt * 64;

        // ---- populate XS: prefetched half + direct half ----
        {
            const float4 a = gather_slot(row, col, base, tid + 1024);
            const float4 b = gather_slot(row, col, base, tid + 1536);
            store_slot(xshp, xslp, tid, r0);
            store_slot(xshp, xslp, tid + 512, r1);
            store_slot(xshp, xslp, tid + 1024, a);
            store_slot(xshp, xslp, tid + 1536, b);
        }
        __syncthreads();

        // issue next tile's half-gather (lands during the 3 GEMM stages)
        const int ntt = tt + gridDim.x;
        if (ntt < n_tiles) {
            r0 = gather_slot(row, col, ntt * 64, tid);
            r1 = gather_slot(row, col, ntt * 64, tid + 512);
        }

        // ---- layer 1: XS -> H1 (attr folded into init, exact fp32) ----
        {
            float d[4][4];
            const float4 ar0 = __ldg(reinterpret_cast<const float4*>(eattr) + (base + m0 + g));
            const float4 ar1 = __ldg(reinterpret_cast<const float4*>(eattr) + (base + m0 + 8 + g));
#pragma unroll
            for (int j = 0; j < 4; ++j) {
                const int c = nb2 + j * 8 + 2 * t;
                const float4 wA = *reinterpret_cast<const float4*>(w1a + c * 4);
                const float4 wB = *reinterpret_cast<const float4*>(w1a + (c + 1) * 4);
                d[j][0] = ar0.x * wA.x + ar0.y * wA.y + ar0.z * wA.z + ar0.w * wA.w;
                d[j][1] = ar0.x * wB.x + ar0.y * wB.y + ar0.z * wB.z + ar0.w * wB.w;
                d[j][2] = ar1.x * wA.x + ar1.y * wA.y + ar1.z * wA.z + ar1.w * wA.w;
                d[j][3] = ar1.x * wB.x + ar1.y * wB.y + ar1.z * wB.z + ar1.w * wB.w;
            }
            kloop<4>(lane, uXSH, uXSL, uW1H, uW1L, m0, nb2, d);
            store_split<4, true>(lane, m0, nb2, d, h1hp, h1lp, b1c);
        }
        __syncthreads();

        // ---- layer 2: H1 -> XS ----
        {
            float d[4][4];
#pragma unroll
            for (int j = 0; j < 4; ++j) { d[j][0] = d[j][1] = d[j][2] = d[j][3] = 0.f; }
            kloop<4>(lane, uH1H, uH1L, uW2H, uW2L, m0, nb2, d);
            store_split<4, true>(lane, m0, nb2, d, xshp, xslp, b2c);
        }
        __syncthreads();

        // ---- layer 3: XS -> messages, scattered straight from registers ----
        {
            float d[2][4];
#pragma unroll
            for (int j = 0; j < 2; ++j) { d[j][0] = d[j][1] = d[j][2] = d[j][3] = 0.f; }
            kloop<2>(lane, uXSH, uXSL, uW3H, uW3L, m0, nb3, d);
            const int e0 = base + m0 + g;
            const int e1 = base + m0 + 8 + g;
#pragma unroll
            for (int j = 0; j < 2; ++j) {
                const int c = nb3 + j * 8 + 2 * t;
                scatter2(col, e0, c, d[j][0] + b3c[j][0], d[j][1] + b3c[j][1]);
                scatter2(col, e1, c, d[j][2] + b3c[j][0], d[j][3] + b3c[j][1]);
            }
        }
        __syncthreads();   // XS/H1 free for next tile
    }
}

// ---------------------------------------------------------------------------
// LSTM kernel. A = [nm|h] (32x128), B = [Wih;Whh] (256x128). bf16 split.
// ---------------------------------------------------------------------------
#define LWCH 0
#define LWCL (LWCH + 65536)
#define LASH (LWCL + 65536)
#define LASL (LASH + 8192)
#define LGT  (LASL + 8192)           // fp32 [32][256]
#define L_SMEM_BYTES (LGT + 32768)   // 180224

__global__ void __launch_bounds__(NTL, 1)
k_lstm(const float* __restrict__ wih, const float* __restrict__ whh,
       const float* __restrict__ bih, const float* __restrict__ bhh) {
    extern __shared__ char smc[];
    const int tid = threadIdx.x, wid = tid >> 5, lane = tid & 31;

    unsigned* wch = (unsigned*)(smc + LWCH);
    unsigned* wcl = (unsigned*)(smc + LWCL);
    unsigned* ash = (unsigned*)(smc + LASH);
    unsigned* asl = (unsigned*)(smc + LASL);
    float*    gt  = (float*)(smc + LGT);

    for (int idx = tid; idx < 256 * 64; idx += NTL) {
        const int n = idx >> 6, wq = idx & 63, k = wq * 2;
        const float v0 = (k < 64) ? wih[n * 64 + k]     : whh[n * 64 + (k - 64)];
        const float v1 = (k < 64) ? wih[n * 64 + k + 1] : whh[n * 64 + (k - 63)];
        unsigned hw, lw;
        split_pack(v0, v1, hw, lw);
        const int off = n * 64 + (wq ^ ((n & 7) << 2));
        wch[off] = hw; wcl[off] = lw;
    }
    __syncthreads();

    const int g = lane >> 2, t = lane & 3;
    const int m0 = (wid & 1) * 16;
    const int nb = (wid >> 1) * 32;

    float bc[4][2];
#pragma unroll
    for (int j = 0; j < 4; ++j) {
        const int c = nb + j * 8 + 2 * t;
        bc[j][0] = __ldg(bih + c) + __ldg(bhh + c);
        bc[j][1] = __ldg(bih + c + 1) + __ldg(bhh + c + 1);
    }

    const unsigned uASH = su32(smc + LASH), uASL = su32(smc + LASL);
    const unsigned uWCH = su32(smc + LWCH), uWCL = su32(smc + LWCL);

    const int n_tiles = (N_SEGS + 31) / 32;  // 938
    for (int tt = blockIdx.x; tt < n_tiles; tt += gridDim.x) {
        const int base = tt * 32;

        // gather A = split([nm | h])
        for (int idx = tid; idx < 32 * 32; idx += NTL) {
            const int i = idx >> 5;
            const int q = idx & 31;
            const int s = base + i;
            float4 v = make_float4(0.f, 0.f, 0.f, 0.f);
            if (s < N_SEGS) {
                if (q < 16) {
                    if (s < N_NODES) {
                        v = reinterpret_cast<const float4*>(g_nm + s * SD)[q];
                    } else {
                        const int f = s - N_NODES;
                        const float4 a = reinterpret_cast<const float4*>(g_f1 + f * SD)[q];
                        const float4 b = reinterpret_cast<const float4*>(g_f2 + f * SD)[q];
                        v = make_float4(a.x + b.x, a.y + b.y, a.z + b.z, a.w + b.w);
                    }
                } else {
                    v = reinterpret_cast<const float4*>(g_h + s * SD)[q - 16];
                }
            }
            unsigned h0, l0, h1, l1;
            split_pack(v.x, v.y, h0, l0);
            split_pack(v.z, v.w, h1, l1);
            const int off = i * 64 + ((q * 2) ^ ((i & 7) << 2));
            *reinterpret_cast<uint2*>(ash + off) = make_uint2(h0, h1);
            *reinterpret_cast<uint2*>(asl + off) = make_uint2(l0, l1);
        }
        __syncthreads();

        // gates = A * [Wih;Whh]^T + b_ih + b_hh   (fp32 out, pitch 256)
        {
            float d[4][4];
#pragma unroll
            for (int j = 0; j < 4; ++j) { d[j][0] = d[j][1] = d[j][2] = d[j][3] = 0.f; }
            kloop<4>(lane, uASH, uASL, uWCH, uWCL, m0, nb, d);
            const int sw = g << 2;
#pragma unroll
            for (int j = 0; j < 4; ++j) {
                const int c = nb + j * 8 + 2 * t;
                const int cc = c ^ sw;
                *reinterpret_cast<float2*>(gt + (m0 + g) * 256 + cc) =
                    make_float2(d[j][0] + bc[j][0], d[j][1] + bc[j][1]);
                *reinterpret_cast<float2*>(gt + (m0 + 8 + g) * 256 + cc) =
                    make_float2(d[j][2] + bc[j][0], d[j][3] + bc[j][1]);
            }
        }
        __syncthreads();

        // elementwise LSTM update + zero node nm
        for (int idx = tid; idx < 32 * 64; idx += NTL) {
            const int i  = idx >> 6;
            const int dd = idx & 63;
            const int s  = base + i;
            if (s < N_SEGS) {
                const int o = dd ^ ((i & 7) << 2);
                const float gi = gt[i * 256 + o];
                const float gf = gt[i * 256 + 64 + o];
                const float gg = gt[i * 256 + 128 + o];
                const float go = gt[i * 256 + 192 + o];
                const float cold = g_c[s * SD + dd];
                const float cn = fsigmoid(gf) * cold + fsigmoid(gi) * ftanh(gg);
                const float hn = fsigmoid(go) * ftanh(cn);
                g_c[s * SD + dd] = cn;
                g_h[s * SD + dd] = hn;
                if (s < N_NODES) g_nm[s * SD + dd] = 0.0f;
            }
        }
        __syncthreads();
    }
}

// ---------------------------------------------------------------------------
__global__ void k_init() {
    int idx = blockIdx.x * blockDim.x + threadIdx.x;
    if (idx >= N_SEGS * SD) return;
    int s = idx >> 6;
    int d = idx & 63;
    g_h[idx] = (s >= N_NODES && d == 0) ? 1.0f : 0.0f;
    g_c[idx] = 0.0f;
    if (s < N_NODES) g_nm[idx] = 0.0f;
}

// ---------------------------------------------------------------------------
// Readout (fp32 SIMT, runs once)
// ---------------------------------------------------------------------------
__device__ __forceinline__ void load_wT(int tid, const float* __restrict__ W,
                                        float* __restrict__ wT,
                                        int N, int K, int WS) {
    for (int idx = tid; idx < N * K; idx += NT_RO) {
        int o = idx / K;
        int k = idx - o * K;
        wT[k * WS + o] = W[idx];
    }
}

template <int N, int K, bool RELU>
__device__ __forceinline__ void gemm_tile64(int tid,
                                            const float* __restrict__ xs,
                                            const float* __restrict__ wT,
                                            const float* __restrict__ bias_g,
                                            float* __restrict__ out) {
    constexpr int OG  = N / 4;
    constexpr int RG  = NT_RO / OG;
    constexpr int EPT = 64 / RG;
    const int oo = tid % OG;
    const int eo = tid / OG;
    const int o  = oo * 4;
    const int e0 = eo * EPT;

    float acc[EPT][4];
    const float4 b4 = __ldg(reinterpret_cast<const float4*>(bias_g) + oo);
#pragma unroll
    for (int ii = 0; ii < EPT; ++ii) {
        acc[ii][0] = b4.x; acc[ii][1] = b4.y; acc[ii][2] = b4.z; acc[ii][3] = b4.w;
    }
#pragma unroll 4
    for (int k = 0; k < K; k += 4) {
        const float4 w0 = *reinterpret_cast<const float4*>(wT + (k + 0) * N + o);
        const float4 w1 = *reinterpret_cast<const float4*>(wT + (k + 1) * N + o);
        const float4 w2 = *reinterpret_cast<const float4*>(wT + (k + 2) * N + o);
        const float4 w3 = *reinterpret_cast<const float4*>(wT + (k + 3) * N + o);
#pragma unroll
        for (int ii = 0; ii < EPT; ++ii) {
            const float4 x4 = *reinterpret_cast<const float4*>(xs + (e0 + ii) * 128 + k);
            acc[ii][0] += x4.x * w0.x + x4.y * w1.x + x4.z * w2.x + x4.w * w3.x;
            acc[ii][1] += x4.x * w0.y + x4.y * w1.y + x4.z * w2.y + x4.w * w3.y;
            acc[ii][2] += x4.x * w0.z + x4.y * w1.z + x4.z * w2.z + x4.w * w3.z;
            acc[ii][3] += x4.x * w0.w + x4.y * w1.w + x4.z * w2.w + x4.w * w3.w;
        }
    }
#pragma unroll
    for (int ii = 0; ii < EPT; ++ii) {
        float4 r;
        r.x = acc[ii][0]; r.y = acc[ii][1]; r.z = acc[ii][2]; r.w = acc[ii][3];
        if (RELU) {
            r.x = fmaxf(r.x, 0.f); r.y = fmaxf(r.y, 0.f);
            r.z = fmaxf(r.z, 0.f); r.w = fmaxf(r.w, 0.f);
        }
        *reinterpret_cast<float4*>(out + (e0 + ii) * N + o) = r;
    }
}

#define R_W1 0
#define R_W2 (R_W1 + 64 * 128)
#define R_W3 (R_W2 + 128 * 128)
#define R_XS (R_W3 + 256)
#define R_H1 (R_XS + 64 * 128)
#define R_LG (R_H1 + 64 * 128)
#define R_SMEM_BYTES ((R_LG + 128) * 4)

__global__ void __launch_bounds__(NT_RO, 1)
k_readout(const float* __restrict__ w1, const float* __restrict__ b1,
          const float* __restrict__ w2, const float* __restrict__ b2,
          const float* __restrict__ w3, const float* __restrict__ b3,
          float* __restrict__ out) {
    extern __shared__ float smf[];
    const int tid = threadIdx.x;

    load_wT(tid, w1, smf + R_W1, 128, 64, 128);
    load_wT(tid, w2, smf + R_W2, 128, 128, 128);
    for (int i = tid; i < 256; i += NT_RO) smf[R_W3 + i] = w3[i];
    __syncthreads();

    const int n_tiles = (N_NODES + 63) / 64;  // 157
    for (int t = blockIdx.x; t < n_tiles; t += gridDim.x) {
        const int base = t * 64;
        for (int idx = tid; idx < 64 * 16; idx += NT_RO) {
            const int i = idx >> 4;
            const int q = idx & 15;
            const int s = base + i;
            float4 v = make_float4(0.f, 0.f, 0.f, 0.f);
            if (s < N_NODES) v = reinterpret_cast<const float4*>(g_h + s * SD)[q];
            reinterpret_cast<float4*>(smf + R_XS + i * 128)[q] = v;
        }
        __syncthreads();

        gemm_tile64<128, 64, true>(tid, smf + R_XS, smf + R_W1, b1, smf + R_H1);
        __syncthreads();
        gemm_tile64<128, 128, true>(tid, smf + R_H1, smf + R_W2, b2, smf + R_XS);
        __syncthreads();

        if (tid < 128) {
            const int i = tid >> 1;
            const int j = tid & 1;
            float acc = __ldg(b3 + j);
#pragma unroll 4
            for (int k = 0; k < 128; ++k)
                acc += smf[R_XS + i * 128 + k] * smf[R_W3 + j * 128 + k];
            smf[R_LG + i * 2 + j] = acc;
        }
        __syncthreads();

        if (tid < 64) {
            const int s = base + tid;
            if (s < N_NODES) {
                const float l0 = smf[R_LG + tid * 2];
                const float l1 = smf[R_LG + tid * 2 + 1];
                const float m  = fmaxf(l0, l1);
                const float e0 = __expf(l0 - m);
                const float e1 = __expf(l1 - m);
                const float inv = 1.0f / (e0 + e1);
                out[s * 2]     = e0 * inv;
                out[s * 2 + 1] = e1 * inv;
            }
        }
        __syncthreads();
    }
}

// ---------------------------------------------------------------------------
extern "C" void kernel_launch(void* const* d_in, const int* in_sizes, int n_in,
                              void* d_out, int out_size) {
    const int*   row   = (const int*)  d_in[0];
    const int*   col   = (const int*)  d_in[1];
    const float* eattr = (const float*)d_in[2];
    const float* mp_w1 = (const float*)d_in[5];
    const float* mp_b1 = (const float*)d_in[6];
    const float* mp_w2 = (const float*)d_in[7];
    const float* mp_b2 = (const float*)d_in[8];
    const float* mp_w3 = (const float*)d_in[9];
    const float* mp_b3 = (const float*)d_in[10];
    const float* w_ih  = (const float*)d_in[11];
    const float* w_hh  = (const float*)d_in[12];
    const float* b_ih  = (const float*)d_in[13];
    const float* b_hh  = (const float*)d_in[14];
    const float* ro_w1 = (const float*)d_in[15];
    const float* ro_b1 = (const float*)d_in[16];
    const float* ro_w2 = (const float*)d_in[17];
    const float* ro_b2 = (const float*)d_in[18];
    const float* ro_w3 = (const float*)d_in[19];
    const float* ro_b3 = (const float*)d_in[20];
    float* out = (float*)d_out;

    cudaFuncSetAttribute(k_edge,    cudaFuncAttributeMaxDynamicSharedMemorySize, E_SMEM_BYTES);
    cudaFuncSetAttribute(k_lstm,    cudaFuncAttributeMaxDynamicSharedMemorySize, L_SMEM_BYTES);
    cudaFuncSetAttribute(k_readout, cudaFuncAttributeMaxDynamicSharedMemorySize, R_SMEM_BYTES);

    k_init<<<(N_SEGS * SD + 255) / 256, 256>>>();

    for (int step = 0; step < N_STEPS; ++step) {
        k_edge<<<NBLK, NTE, E_SMEM_BYTES>>>(row, col, eattr,
                                            mp_w1, mp_b1, mp_w2, mp_b2, mp_w3, mp_b3);
        k_lstm<<<NBLK, NTL, L_SMEM_BYTES>>>(w_ih, w_hh, b_ih, b_hh);
    }

    k_readout<<<NBLK, NT_RO, R_SMEM_BYTES>>>(ro_w1, ro_b1, ro_w2, ro_b2, ro_w3, ro_b3, out);
}

// round 8
// speedup vs baseline: 3.6164x; 1.0032x over previous
#include <cuda_runtime.h>
#include <cuda_bf16.h>

// ---------------------------------------------------------------------------
// VGNN sparse GNN. Round 7: bf16 hi/lo split MMA with interleaved accumulator
// chains (dep distance 1 -> 4), register-cached biases, prefetched gather,
// register scatter. Same math/order as Round 6 (bit-identical epilogues).
// ---------------------------------------------------------------------------

#define N_NODES   10000
#define N_FACTORS 20000
#define N_SEGS    30000
#define N_EDGES   80000
#define SD        64
#define N_STEPS   10
#define NTE       512
#define NTL       512
#define NT_RO     256
#define NBLK      148

__device__ float g_h [N_SEGS * SD];
__device__ float g_c [N_SEGS * SD];
__device__ float g_nm[N_NODES * SD];     // node-targeted messages (atomics)
__device__ float g_f1[N_FACTORS * SD];   // factor messages, edges [0,20000)
__device__ float g_f2[N_FACTORS * SD];   // factor messages, edges [20000,40000)

__device__ __forceinline__ float fsigmoid(float x) {
    return 1.0f / (1.0f + __expf(-x));
}
__device__ __forceinline__ float ftanh(float x) {
    return 2.0f * fsigmoid(2.0f * x) - 1.0f;
}

__device__ __forceinline__ unsigned su32(const void* p) {
    return (unsigned)__cvta_generic_to_shared(p);
}

#define LDSM4(r0, r1, r2, r3, addr)                                          \
    asm volatile("ldmatrix.sync.aligned.m8n8.x4.shared.b16 {%0,%1,%2,%3},[%4];" \
                 : "=r"(r0), "=r"(r1), "=r"(r2), "=r"(r3) : "r"(addr))

__device__ __forceinline__ void mma16(float (&d)[4],
                                      unsigned a0, unsigned a1, unsigned a2, unsigned a3,
                                      unsigned b0, unsigned b1) {
    asm volatile(
        "mma.sync.aligned.m16n8k16.row.col.f32.bf16.bf16.f32 "
        "{%0,%1,%2,%3},{%4,%5,%6,%7},{%8,%9},{%0,%1,%2,%3};"
        : "+f"(d[0]), "+f"(d[1]), "+f"(d[2]), "+f"(d[3])
        : "r"(a0), "r"(a1), "r"(a2), "r"(a3), "r"(b0), "r"(b1));
}

// split (v0,v1) -> packed bf16x2 hi word (lo16=v0) and lo (residual) word
__device__ __forceinline__ void split_pack(float v0, float v1,
                                           unsigned& hw, unsigned& lw) {
    asm("cvt.rn.bf16x2.f32 %0, %1, %2;" : "=r"(hw) : "f"(v1), "f"(v0));
    const float h0 = __uint_as_float(hw << 16);
    const float h1 = __uint_as_float(hw & 0xffff0000u);
    const float r0 = v0 - h0;
    const float r1 = v1 - h1;
    asm("cvt.rn.bf16x2.f32 %0, %1, %2;" : "=r"(lw) : "f"(r1), "f"(r0));
}

// ---------------------------------------------------------------------------
// bf16 arrays: [rows][128] bf16, 256 B/row = 64 words/row.
// word (row, w) at row*64 + (w ^ ((row&7)<<2)).   (LDSM-compatible swizzle)
//
// kloop: per chunk, ALL B fragments loaded first, then 3 passes of MMAs
// round-robin over the accumulators (dep distance NSUB instead of 1).
// Per-accumulator MMA order is unchanged vs previous rounds (hh, hl, lh).
// ---------------------------------------------------------------------------
template <int NSUB>
__device__ __forceinline__ void kloop(int lane,
                                      unsigned Ahi, unsigned Alo,
                                      unsigned Bhi, unsigned Blo,
                                      int m0, int nbase,
                                      float (&d)[NSUB][4]) {
    const int l7 = lane & 7;
    const int sw = l7 << 2;
    const unsigned a_row = (unsigned)(m0 + ((lane >> 3) & 1) * 8 + l7) * 256;
    const int a_kadd = (lane >> 4) * 4;
    const int b_kadd = ((lane >> 3) & 1) * 4;
    constexpr int NP = NSUB / 2;
    unsigned b_row[NP];
#pragma unroll
    for (int p = 0; p < NP; ++p)
        b_row[p] = (unsigned)(nbase + p * 16 + (lane >> 4) * 8 + l7) * 256;

#pragma unroll
    for (int ch = 0; ch < 8; ++ch) {
        const unsigned aoff = a_row + ((unsigned)((ch * 8 + a_kadd) ^ sw) << 2);
        unsigned ah[4], al[4];
        LDSM4(ah[0], ah[1], ah[2], ah[3], Ahi + aoff);
        LDSM4(al[0], al[1], al[2], al[3], Alo + aoff);
        const unsigned bk = (unsigned)((ch * 8 + b_kadd) ^ sw) << 2;
        unsigned bh[NP][4], bl[NP][4];
#pragma unroll
        for (int p = 0; p < NP; ++p) {
            LDSM4(bh[p][0], bh[p][1], bh[p][2], bh[p][3], Bhi + b_row[p] + bk);
            LDSM4(bl[p][0], bl[p][1], bl[p][2], bl[p][3], Blo + b_row[p] + bk);
        }
        // pass 1: ah * bh   (each accumulator touched once per pass)
#pragma unroll
        for (int p = 0; p < NP; ++p) {
            mma16(d[2 * p],     ah[0], ah[1], ah[2], ah[3], bh[p][0], bh[p][1]);
            mma16(d[2 * p + 1], ah[0], ah[1], ah[2], ah[3], bh[p][2], bh[p][3]);
        }
        // pass 2: ah * bl
#pragma unroll
        for (int p = 0; p < NP; ++p) {
            mma16(d[2 * p],     ah[0], ah[1], ah[2], ah[3], bl[p][0], bl[p][1]);
            mma16(d[2 * p + 1], ah[0], ah[1], ah[2], ah[3], bl[p][2], bl[p][3]);
        }
        // pass 3: al * bh
#pragma unroll
        for (int p = 0; p < NP; ++p) {
            mma16(d[2 * p],     al[0], al[1], al[2], al[3], bh[p][0], bh[p][1]);
            mma16(d[2 * p + 1], al[0], al[1], al[2], al[3], bh[p][2], bh[p][3]);
        }
    }
}

// epilogue: +cached bias, relu, split to hi/lo bf16 arrays (pitch 64 words)
template <int NSUB, bool RELU>
__device__ __forceinline__ void store_split(int lane, int m0, int nbase,
                                            float (&d)[NSUB][4],
                                            unsigned* __restrict__ OutHi,
                                            unsigned* __restrict__ OutLo,
                                            const float (&bc)[NSUB][2]) {
    const int g = lane >> 2, t = lane & 3;
    const int sw = g << 2;
    unsigned* oh0 = OutHi + (m0 + g) * 64;
    unsigned* oh1 = OutHi + (m0 + 8 + g) * 64;
    unsigned* ol0 = OutLo + (m0 + g) * 64;
    unsigned* ol1 = OutLo + (m0 + 8 + g) * 64;
#pragma unroll
    for (int j = 0; j < NSUB; ++j) {
        const int c = nbase + j * 8 + 2 * t;
        const float bx = bc[j][0];
        const float by = bc[j][1];
        float v0 = d[j][0] + bx, v1 = d[j][1] + by;
        float v2 = d[j][2] + bx, v3 = d[j][3] + by;
        if (RELU) {
            v0 = fmaxf(v0, 0.f); v1 = fmaxf(v1, 0.f);
            v2 = fmaxf(v2, 0.f); v3 = fmaxf(v3, 0.f);
        }
        unsigned hw0, lw0, hw1, lw1;
        split_pack(v0, v1, hw0, lw0);
        split_pack(v2, v3, hw1, lw1);
        const int wq = (c >> 1) ^ sw;
        oh0[wq] = hw0; ol0[wq] = lw0;
        oh1[wq] = hw1; ol1[wq] = lw1;
    }
}

// gather helpers ------------------------------------------------------------
__device__ __forceinline__ float4 gather_slot(const int* __restrict__ row,
                                              const int* __restrict__ col,
                                              int base, int idx) {
    const int i = idx >> 5, q = idx & 31;
    const int e = base + i;
    const int n = (q < 16) ? __ldg(row + e) : __ldg(col + e);
    const int qq = (q < 16) ? q : q - 16;
    return __ldg(reinterpret_cast<const float4*>(g_h + n * SD) + qq);
}

__device__ __forceinline__ void store_slot(unsigned* __restrict__ xsh,
                                           unsigned* __restrict__ xsl,
                                           int idx, float4 v) {
    const int i = idx >> 5, q = idx & 31;
    unsigned h0, l0, h1, l1;
    split_pack(v.x, v.y, h0, l0);
    split_pack(v.z, v.w, h1, l1);
    const int off = i * 64 + ((q * 2) ^ ((i & 7) << 2));
    *reinterpret_cast<uint2*>(xsh + off) = make_uint2(h0, h1);
    *reinterpret_cast<uint2*>(xsl + off) = make_uint2(l0, l1);
}

// direct message scatter from registers
__device__ __forceinline__ void scatter2(const int* __restrict__ col,
                                         int e, int c, float v0, float v1) {
    if (e < 20000) {
        *reinterpret_cast<float2*>(g_f1 + e * SD + c) = make_float2(v0, v1);
    } else if (e < 40000) {
        *reinterpret_cast<float2*>(g_f2 + (e - 20000) * SD + c) = make_float2(v0, v1);
    } else {
        const int s = __ldg(col + e);
        atomicAdd(g_nm + s * SD + c, v0);
        atomicAdd(g_nm + s * SD + c + 1, v1);
    }
}

// ---------------------------------------------------------------------------
// Edge kernel smem layout (byte offsets):
// ---------------------------------------------------------------------------
#define W1H 0
#define W1L (W1H + 32768)
#define W2H (W1L + 32768)
#define W2L (W2H + 32768)
#define W3H (W2L + 32768)
#define W3L (W3H + 16384)
#define XSH (W3L + 16384)
#define XSL (XSH + 16384)
#define H1H (XSL + 16384)
#define H1L (H1H + 16384)
#define W1A (H1L + 16384)           // fp32 [128][4]
#define E_SMEM_BYTES (W1A + 2048)   // 231424 <= 232448

__global__ void __launch_bounds__(NTE, 1)
k_edge(const int* __restrict__ row, const int* __restrict__ col,
       const float* __restrict__ eattr,
       const float* __restrict__ w1, const float* __restrict__ b1,
       const float* __restrict__ w2, const float* __restrict__ b2,
       const float* __restrict__ w3, const float* __restrict__ b3) {
    extern __shared__ char smc[];
    const int tid = threadIdx.x, wid = tid >> 5, lane = tid & 31;

    unsigned* w1hp = (unsigned*)(smc + W1H);
    unsigned* w1lp = (unsigned*)(smc + W1L);
    unsigned* w2hp = (unsigned*)(smc + W2H);
    unsigned* w2lp = (unsigned*)(smc + W2L);
    unsigned* w3hp = (unsigned*)(smc + W3H);
    unsigned* w3lp = (unsigned*)(smc + W3L);
    unsigned* xshp = (unsigned*)(smc + XSH);
    unsigned* xslp = (unsigned*)(smc + XSL);
    unsigned* h1hp = (unsigned*)(smc + H1H);
    unsigned* h1lp = (unsigned*)(smc + H1L);
    float*    w1a  = (float*)(smc + W1A);

    // ---- weight pre-split ----
    for (int idx = tid; idx < 128 * 64; idx += NTE) {
        const int n = idx >> 6, wq = idx & 63, k = wq * 2;
        const int off = n * 64 + (wq ^ ((n & 7) << 2));
        unsigned hw, lw;
        split_pack(w1[n * 132 + k], w1[n * 132 + k + 1], hw, lw);
        w1hp[off] = hw; w1lp[off] = lw;
        split_pack(w2[n * 128 + k], w2[n * 128 + k + 1], hw, lw);
        w2hp[off] = hw; w2lp[off] = lw;
    }
    for (int idx = tid; idx < 64 * 64; idx += NTE) {
        const int n = idx >> 6, wq = idx & 63, k = wq * 2;
        const int off = n * 64 + (wq ^ ((n & 7) << 2));
        unsigned hw, lw;
        split_pack(w3[n * 128 + k], w3[n * 128 + k + 1], hw, lw);
        w3hp[off] = hw; w3lp[off] = lw;
    }
    for (int idx = tid; idx < 512; idx += NTE)
        w1a[idx] = w1[(idx >> 2) * 132 + 128 + (idx & 3)];
    __syncthreads();

    const int g = lane >> 2, t = lane & 3;
    const int m0  = (wid & 3) * 16;
    const int nb2 = (wid >> 2) * 32;   // layers 1,2 (N=128)
    const int nb3 = (wid >> 2) * 16;   // layer 3   (N=64)

    // register-cached bias slices (loop-invariant)
    float b1c[4][2], b2c[4][2], b3c[2][2];
#pragma unroll
    for (int j = 0; j < 4; ++j) {
        b1c[j][0] = __ldg(b1 + nb2 + j * 8 + 2 * t);
        b1c[j][1] = __ldg(b1 + nb2 + j * 8 + 2 * t + 1);
        b2c[j][0] = __ldg(b2 + nb2 + j * 8 + 2 * t);
        b2c[j][1] = __ldg(b2 + nb2 + j * 8 + 2 * t + 1);
    }
#pragma unroll
    for (int j = 0; j < 2; ++j) {
        b3c[j][0] = __ldg(b3 + nb3 + j * 8 + 2 * t);
        b3c[j][1] = __ldg(b3 + nb3 + j * 8 + 2 * t + 1);
    }

    const unsigned uXSH = su32(smc + XSH), uXSL = su32(smc + XSL);
    const unsigned uH1H = su32(smc + H1H), uH1L = su32(smc + H1L);
    const unsigned uW1H = su32(smc + W1H), uW1L = su32(smc + W1L);
    const unsigned uW2H = su32(smc + W2H), uW2L = su32(smc + W2L);
    const unsigned uW3H = su32(smc + W3H), uW3L = su32(smc + W3L);

    const int n_tiles = N_EDGES / 64;  // 1250

    // prefetch first tile's half-gather into registers
    int tt = blockIdx.x;
    float4 r0, r1;
    if (tt < n_tiles) {
        r0 = gather_slot(row, col, tt * 64, tid);
        r1 = gather_slot(row, col, tt * 64, tid + 512);
    }

    for (; tt < n_tiles; tt += gridDim.x) {
        const int base = tt * 64;

        // ---- populate XS: prefetched half + direct half ----
        {
            const float4 a = gather_slot(row, col, base, tid + 1024);
            const float4 b = gather_slot(row, col, base, tid + 1536);
            store_slot(xshp, xslp, tid, r0);
            store_slot(xshp, xslp, tid + 512, r1);
            store_slot(xshp, xslp, tid + 1024, a);
            store_slot(xshp, xslp, tid + 1536, b);
        }
        __syncthreads();

        // issue next tile's half-gather (lands during the 3 GEMM stages)
        const int ntt = tt + gridDim.x;
        if (ntt < n_tiles) {
            r0 = gather_slot(row, col, ntt * 64, tid);
            r1 = gather_slot(row, col, ntt * 64, tid + 512);
        }

        // ---- layer 1: XS -> H1 (attr folded into init, exact fp32) ----
        {
            float d[4][4];
            const float4 ar0 = __ldg(reinterpret_cast<const float4*>(eattr) + (base + m0 + g));
            const float4 ar1 = __ldg(reinterpret_cast<const float4*>(eattr) + (base + m0 + 8 + g));
#pragma unroll
            for (int j = 0; j < 4; ++j) {
                const int c = nb2 + j * 8 + 2 * t;
                const float4 wA = *reinterpret_cast<const float4*>(w1a + c * 4);
                const float4 wB = *reinterpret_cast<const float4*>(w1a + (c + 1) * 4);
                d[j][0] = ar0.x * wA.x + ar0.y * wA.y + ar0.z * wA.z + ar0.w * wA.w;
                d[j][1] = ar0.x * wB.x + ar0.y * wB.y + ar0.z * wB.z + ar0.w * wB.w;
                d[j][2] = ar1.x * wA.x + ar1.y * wA.y + ar1.z * wA.z + ar1.w * wA.w;
                d[j][3] = ar1.x * wB.x + ar1.y * wB.y + ar1.z * wB.z + ar1.w * wB.w;
            }
            kloop<4>(lane, uXSH, uXSL, uW1H, uW1L, m0, nb2, d);
            store_split<4, true>(lane, m0, nb2, d, h1hp, h1lp, b1c);
        }
        __syncthreads();

        // ---- layer 2: H1 -> XS ----
        {
            float d[4][4];
#pragma unroll
            for (int j = 0; j < 4; ++j) { d[j][0] = d[j][1] = d[j][2] = d[j][3] = 0.f; }
            kloop<4>(lane, uH1H, uH1L, uW2H, uW2L, m0, nb2, d);
            store_split<4, true>(lane, m0, nb2, d, xshp, xslp, b2c);
        }
        __syncthreads();

        // ---- layer 3: XS -> messages, scattered straight from registers ----
        {
            float d[2][4];
#pragma unroll
            for (int j = 0; j < 2; ++j) { d[j][0] = d[j][1] = d[j][2] = d[j][3] = 0.f; }
            kloop<2>(lane, uXSH, uXSL, uW3H, uW3L, m0, nb3, d);
            const int e0 = base + m0 + g;
            const int e1 = base + m0 + 8 + g;
#pragma unroll
            for (int j = 0; j < 2; ++j) {
                const int c = nb3 + j * 8 + 2 * t;
                scatter2(col, e0, c, d[j][0] + b3c[j][0], d[j][1] + b3c[j][1]);
                scatter2(col, e1, c, d[j][2] + b3c[j][0], d[j][3] + b3c[j][1]);
            }
        }
        __syncthreads();   // XS/H1 free for next tile
    }
}

// ---------------------------------------------------------------------------
// LSTM kernel. A = [nm|h] (32x128), B = [Wih;Whh] (256x128). bf16 split.
// ---------------------------------------------------------------------------
#define LWCH 0
#define LWCL (LWCH + 65536)
#define LASH (LWCL + 65536)
#define LASL (LASH + 8192)
#define LGT  (LASL + 8192)           // fp32 [32][256]
#define L_SMEM_BYTES (LGT + 32768)   // 180224

__global__ void __launch_bounds__(NTL, 1)
k_lstm(const float* __restrict__ wih, const float* __restrict__ whh,
       const float* __restrict__ bih, const float* __restrict__ bhh) {
    extern __shared__ char smc[];
    const int tid = threadIdx.x, wid = tid >> 5, lane = tid & 31;

    unsigned* wch = (unsigned*)(smc + LWCH);
    unsigned* wcl = (unsigned*)(smc + LWCL);
    unsigned* ash = (unsigned*)(smc + LASH);
    unsigned* asl = (unsigned*)(smc + LASL);
    float*    gt  = (float*)(smc + LGT);

    for (int idx = tid; idx < 256 * 64; idx += NTL) {
        const int n = idx >> 6, wq = idx & 63, k = wq * 2;
        const float v0 = (k < 64) ? wih[n * 64 + k]     : whh[n * 64 + (k - 64)];
        const float v1 = (k < 64) ? wih[n * 64 + k + 1] : whh[n * 64 + (k - 63)];
        unsigned hw, lw;
        split_pack(v0, v1, hw, lw);
        const int off = n * 64 + (wq ^ ((n & 7) << 2));
        wch[off] = hw; wcl[off] = lw;
    }
    __syncthreads();

    const int g = lane >> 2, t = lane & 3;
    const int m0 = (wid & 1) * 16;
    const int nb = (wid >> 1) * 32;

    float bc[4][2];
#pragma unroll
    for (int j = 0; j < 4; ++j) {
        const int c = nb + j * 8 + 2 * t;
        bc[j][0] = __ldg(bih + c) + __ldg(bhh + c);
        bc[j][1] = __ldg(bih + c + 1) + __ldg(bhh + c + 1);
    }

    const unsigned uASH = su32(smc + LASH), uASL = su32(smc + LASL);
    const unsigned uWCH = su32(smc + LWCH), uWCL = su32(smc + LWCL);

    const int n_tiles = (N_SEGS + 31) / 32;  // 938
    for (int tt = blockIdx.x; tt < n_tiles; tt += gridDim.x) {
        const int base = tt * 32;

        // gather A = split([nm | h])
        for (int idx = tid; idx < 32 * 32; idx += NTL) {
            const int i = idx >> 5;
            const int q = idx & 31;
            const int s = base + i;
            float4 v = make_float4(0.f, 0.f, 0.f, 0.f);
            if (s < N_SEGS) {
                if (q < 16) {
                    if (s < N_NODES) {
                        v = reinterpret_cast<const float4*>(g_nm + s * SD)[q];
                    } else {
                        const int f = s - N_NODES;
                        const float4 a = reinterpret_cast<const float4*>(g_f1 + f * SD)[q];
                        const float4 b = reinterpret_cast<const float4*>(g_f2 + f * SD)[q];
                        v = make_float4(a.x + b.x, a.y + b.y, a.z + b.z, a.w + b.w);
                    }
                } else {
                    v = reinterpret_cast<const float4*>(g_h + s * SD)[q - 16];
                }
            }
            unsigned h0, l0, h1, l1;
            split_pack(v.x, v.y, h0, l0);
            split_pack(v.z, v.w, h1, l1);
            const int off = i * 64 + ((q * 2) ^ ((i & 7) << 2));
            *reinterpret_cast<uint2*>(ash + off) = make_uint2(h0, h1);
            *reinterpret_cast<uint2*>(asl + off) = make_uint2(l0, l1);
        }
        __syncthreads();

        // gates = A * [Wih;Whh]^T + b_ih + b_hh   (fp32 out, pitch 256)
        {
            float d[4][4];
#pragma unroll
            for (int j = 0; j < 4; ++j) { d[j][0] = d[j][1] = d[j][2] = d[j][3] = 0.f; }
            kloop<4>(lane, uASH, uASL, uWCH, uWCL, m0, nb, d);
            const int sw = g << 2;
#pragma unroll
            for (int j = 0; j < 4; ++j) {
                const int c = nb + j * 8 + 2 * t;
                const int cc = c ^ sw;
                *reinterpret_cast<float2*>(gt + (m0 + g) * 256 + cc) =
                    make_float2(d[j][0] + bc[j][0], d[j][1] + bc[j][1]);
                *reinterpret_cast<float2*>(gt + (m0 + 8 + g) * 256 + cc) =
                    make_float2(d[j][2] + bc[j][0], d[j][3] + bc[j][1]);
            }
        }
        __syncthreads();

        // elementwise LSTM update + zero node nm
        for (int idx = tid; idx < 32 * 64; idx += NTL) {
            const int i  = idx >> 6;
            const int dd = idx & 63;
            const int s  = base + i;
            if (s < N_SEGS) {
                const int o = dd ^ ((i & 7) << 2);
                const float gi = gt[i * 256 + o];
                const float gf = gt[i * 256 + 64 + o];
                const float gg = gt[i * 256 + 128 + o];
                const float go = gt[i * 256 + 192 + o];
                const float cold = g_c[s * SD + dd];
                const float cn = fsigmoid(gf) * cold + fsigmoid(gi) * ftanh(gg);
                const float hn = fsigmoid(go) * ftanh(cn);
                g_c[s * SD + dd] = cn;
                g_h[s * SD + dd] = hn;
                if (s < N_NODES) g_nm[s * SD + dd] = 0.0f;
            }
        }
        __syncthreads();
    }
}

// ---------------------------------------------------------------------------
__global__ void k_init() {
    int idx = blockIdx.x * blockDim.x + threadIdx.x;
    if (idx >= N_SEGS * SD) return;
    int s = idx >> 6;
    int d = idx & 63;
    g_h[idx] = (s >= N_NODES && d == 0) ? 1.0f : 0.0f;
    g_c[idx] = 0.0f;
    if (s < N_NODES) g_nm[idx] = 0.0f;
}

// ---------------------------------------------------------------------------
// Readout (fp32 SIMT, runs once)
// ---------------------------------------------------------------------------
__device__ __forceinline__ void load_wT(int tid, const float* __restrict__ W,
                                        float* __restrict__ wT,
                                        int N, int K, int WS) {
    for (int idx = tid; idx < N * K; idx += NT_RO) {
        int o = idx / K;
        int k = idx - o * K;
        wT[k * WS + o] = W[idx];
    }
}

template <int N, int K, bool RELU>
__device__ __forceinline__ void gemm_tile64(int tid,
                                            const float* __restrict__ xs,
                                            const float* __restrict__ wT,
                                            const float* __restrict__ bias_g,
                                            float* __restrict__ out) {
    constexpr int OG  = N / 4;
    constexpr int RG  = NT_RO / OG;
    constexpr int EPT = 64 / RG;
    const int oo = tid % OG;
    const int eo = tid / OG;
    const int o  = oo * 4;
    const int e0 = eo * EPT;

    float acc[EPT][4];
    const float4 b4 = __ldg(reinterpret_cast<const float4*>(bias_g) + oo);
#pragma unroll
    for (int ii = 0; ii < EPT; ++ii) {
        acc[ii][0] = b4.x; acc[ii][1] = b4.y; acc[ii][2] = b4.z; acc[ii][3] = b4.w;
    }
#pragma unroll 4
    for (int k = 0; k < K; k += 4) {
        const float4 w0 = *reinterpret_cast<const float4*>(wT + (k + 0) * N + o);
        const float4 w1 = *reinterpret_cast<const float4*>(wT + (k + 1) * N + o);
        const float4 w2 = *reinterpret_cast<const float4*>(wT + (k + 2) * N + o);
        const float4 w3 = *reinterpret_cast<const float4*>(wT + (k + 3) * N + o);
#pragma unroll
        for (int ii = 0; ii < EPT; ++ii) {
            const float4 x4 = *reinterpret_cast<const float4*>(xs + (e0 + ii) * 128 + k);
            acc[ii][0] += x4.x * w0.x + x4.y * w1.x + x4.z * w2.x + x4.w * w3.x;
            acc[ii][1] += x4.x * w0.y + x4.y * w1.y + x4.z * w2.y + x4.w * w3.y;
            acc[ii][2] += x4.x * w0.z + x4.y * w1.z + x4.z * w2.z + x4.w * w3.z;
            acc[ii][3] += x4.x * w0.w + x4.y * w1.w + x4.z * w2.w + x4.w * w3.w;
        }
    }
#pragma unroll
    for (int ii = 0; ii < EPT; ++ii) {
        float4 r;
        r.x = acc[ii][0]; r.y = acc[ii][1]; r.z = acc[ii][2]; r.w = acc[ii][3];
        if (RELU) {
            r.x = fmaxf(r.x, 0.f); r.y = fmaxf(r.y, 0.f);
            r.z = fmaxf(r.z, 0.f); r.w = fmaxf(r.w, 0.f);
        }
        *reinterpret_cast<float4*>(out + (e0 + ii) * N + o) = r;
    }
}

#define R_W1 0
#define R_W2 (R_W1 + 64 * 128)
#define R_W3 (R_W2 + 128 * 128)
#define R_XS (R_W3 + 256)
#define R_H1 (R_XS + 64 * 128)
#define R_LG (R_H1 + 64 * 128)
#define R_SMEM_BYTES ((R_LG + 128) * 4)

__global__ void __launch_bounds__(NT_RO, 1)
k_readout(const float* __restrict__ w1, const float* __restrict__ b1,
          const float* __restrict__ w2, const float* __restrict__ b2,
          const float* __restrict__ w3, const float* __restrict__ b3,
          float* __restrict__ out) {
    extern __shared__ float smf[];
    const int tid = threadIdx.x;

    load_wT(tid, w1, smf + R_W1, 128, 64, 128);
    load_wT(tid, w2, smf + R_W2, 128, 128, 128);
    for (int i = tid; i < 256; i += NT_RO) smf[R_W3 + i] = w3[i];
    __syncthreads();

    const int n_tiles = (N_NODES + 63) / 64;  // 157
    for (int t = blockIdx.x; t < n_tiles; t += gridDim.x) {
        const int base = t * 64;
        for (int idx = tid; idx < 64 * 16; idx += NT_RO) {
            const int i = idx >> 4;
            const int q = idx & 15;
            const int s = base + i;
            float4 v = make_float4(0.f, 0.f, 0.f, 0.f);
            if (s < N_NODES) v = reinterpret_cast<const float4*>(g_h + s * SD)[q];
            reinterpret_cast<float4*>(smf + R_XS + i * 128)[q] = v;
        }
        __syncthreads();

        gemm_tile64<128, 64, true>(tid, smf + R_XS, smf + R_W1, b1, smf + R_H1);
        __syncthreads();
        gemm_tile64<128, 128, true>(tid, smf + R_H1, smf + R_W2, b2, smf + R_XS);
        __syncthreads();

        if (tid < 128) {
            const int i = tid >> 1;
            const int j = tid & 1;
            float acc = __ldg(b3 + j);
#pragma unroll 4
            for (int k = 0; k < 128; ++k)
                acc += smf[R_XS + i * 128 + k] * smf[R_W3 + j * 128 + k];
            smf[R_LG + i * 2 + j] = acc;
        }
        __syncthreads();

        if (tid < 64) {
            const int s = base + tid;
            if (s < N_NODES) {
                const float l0 = smf[R_LG + tid * 2];
                const float l1 = smf[R_LG + tid * 2 + 1];
                const float m  = fmaxf(l0, l1);
                const float e0 = __expf(l0 - m);
                const float e1 = __expf(l1 - m);
                const float inv = 1.0f / (e0 + e1);
                out[s * 2]     = e0 * inv;
                out[s * 2 + 1] = e1 * inv;
            }
        }
        __syncthreads();
    }
}

// ---------------------------------------------------------------------------
extern "C" void kernel_launch(void* const* d_in, const int* in_sizes, int n_in,
                              void* d_out, int out_size) {
    const int*   row   = (const int*)  d_in[0];
    const int*   col   = (const int*)  d_in[1];
    const float* eattr = (const float*)d_in[2];
    const float* mp_w1 = (const float*)d_in[5];
    const float* mp_b1 = (const float*)d_in[6];
    const float* mp_w2 = (const float*)d_in[7];
    const float* mp_b2 = (const float*)d_in[8];
    const float* mp_w3 = (const float*)d_in[9];
    const float* mp_b3 = (const float*)d_in[10];
    const float* w_ih  = (const float*)d_in[11];
    const float* w_hh  = (const float*)d_in[12];
    const float* b_ih  = (const float*)d_in[13];
    const float* b_hh  = (const float*)d_in[14];
    const float* ro_w1 = (const float*)d_in[15];
    const float* ro_b1 = (const float*)d_in[16];
    const float* ro_w2 = (const float*)d_in[17];
    const float* ro_b2 = (const float*)d_in[18];
    const float* ro_w3 = (const float*)d_in[19];
    const float* ro_b3 = (const float*)d_in[20];
    float* out = (float*)d_out;

    cudaFuncSetAttribute(k_edge,    cudaFuncAttributeMaxDynamicSharedMemorySize, E_SMEM_BYTES);
    cudaFuncSetAttribute(k_lstm,    cudaFuncAttributeMaxDynamicSharedMemorySize, L_SMEM_BYTES);
    cudaFuncSetAttribute(k_readout, cudaFuncAttributeMaxDynamicSharedMemorySize, R_SMEM_BYTES);

    k_init<<<(N_SEGS * SD + 255) / 256, 256>>>();

    for (int step = 0; step < N_STEPS; ++step) {
        k_edge<<<NBLK, NTE, E_SMEM_BYTES>>>(row, col, eattr,
                                            mp_w1, mp_b1, mp_w2, mp_b2, mp_w3, mp_b3);
        k_lstm<<<NBLK, NTL, L_SMEM_BYTES>>>(w_ih, w_hh, b_ih, b_hh);
    }

    k_readout<<<NBLK, NT_RO, R_SMEM_BYTES>>>(ro_w1, ro_b1, ro_w2, ro_b2, ro_w3, ro_b3, out);
}